// round 3
// baseline (speedup 1.0000x reference)
#include <cuda_runtime.h>
#include <cstdint>

// Problem constants
// x:         (16, 1024, 512)
// kernels:   (3, 512, 1024)
// biases:    (3, 1024)
// attn_self: (3, 1024)
// attn_neigh:(3, 1024)
// out:       (4, 16, 1024, 1024) fp32
#define H 3
#define BATCH 16
#define NN 1024          // N (nodes)
#define FF 512           // F (in features)
#define FK 1024          // F_ (out features)
#define M1 (BATCH * NN)  // 16384 rows for GEMM1

// 201 MB scratch for feats[h][b][n][k]
__device__ float g_feats[(size_t)H * BATCH * NN * FK];
__device__ float g_sself[H * BATCH * NN];
__device__ float g_sneigh[H * BATCH * NN];

// ---------------------------------------------------------------------------
// GEMM1: feats[h] = X (16384 x 512) @ W[h] (512 x 1024)
// classic 128x128x8 tile, 256 threads, 8x8 per-thread microtile, float4 I/O
// ---------------------------------------------------------------------------
__global__ __launch_bounds__(256) void gemm1_kernel(const float* __restrict__ X,
                                                    const float* __restrict__ W) {
    const int h    = blockIdx.z;
    const int cRow = blockIdx.y;   // 0..127
    const int cCol = blockIdx.x;   // 0..7

    __shared__ float As[8 * 128];
    __shared__ float Bs[8 * 128];

    const int tid       = threadIdx.x;
    const int threadCol = tid & 15;        // 0..15
    const int threadRow = tid >> 4;        // 0..15
    const int innerRowA = tid >> 1;        // 0..127
    const int innerColA = tid & 1;         // 0..1 (float4 index)
    const int innerRowB = tid >> 5;        // 0..7
    const int innerColB = tid & 31;        // 0..31 (float4 index)

    const float* A = X + (size_t)cRow * 128 * FF;
    const float* B = W + (size_t)h * FF * FK + (size_t)cCol * 128;
    float*       C = g_feats + (size_t)h * M1 * FK +
                     (size_t)cRow * 128 * FK + (size_t)cCol * 128;

    float acc[64];
#pragma unroll
    for (int i = 0; i < 64; i++) acc[i] = 0.f;
    float regM[8], regN[8];

    for (int bk = 0; bk < FF; bk += 8) {
        float4 a4 = *reinterpret_cast<const float4*>(A + (size_t)innerRowA * FF + innerColA * 4);
        As[(innerColA * 4 + 0) * 128 + innerRowA] = a4.x;
        As[(innerColA * 4 + 1) * 128 + innerRowA] = a4.y;
        As[(innerColA * 4 + 2) * 128 + innerRowA] = a4.z;
        As[(innerColA * 4 + 3) * 128 + innerRowA] = a4.w;
        *reinterpret_cast<float4*>(&Bs[innerRowB * 128 + innerColB * 4]) =
            *reinterpret_cast<const float4*>(B + (size_t)innerRowB * FK + innerColB * 4);
        __syncthreads();
        A += 8;
        B += (size_t)8 * FK;
#pragma unroll
        for (int k = 0; k < 8; k++) {
            *reinterpret_cast<float4*>(&regM[0]) = *reinterpret_cast<float4*>(&As[k * 128 + threadRow * 8]);
            *reinterpret_cast<float4*>(&regM[4]) = *reinterpret_cast<float4*>(&As[k * 128 + threadRow * 8 + 4]);
            *reinterpret_cast<float4*>(&regN[0]) = *reinterpret_cast<float4*>(&Bs[k * 128 + threadCol * 8]);
            *reinterpret_cast<float4*>(&regN[4]) = *reinterpret_cast<float4*>(&Bs[k * 128 + threadCol * 8 + 4]);
#pragma unroll
            for (int i = 0; i < 8; i++)
#pragma unroll
                for (int j = 0; j < 8; j++) acc[i * 8 + j] += regM[i] * regN[j];
        }
        __syncthreads();
    }

#pragma unroll
    for (int i = 0; i < 8; i++) {
        float* crow = C + (size_t)(threadRow * 8 + i) * FK + threadCol * 8;
#pragma unroll
        for (int j = 0; j < 8; j += 4) {
            float4 v = make_float4(acc[i * 8 + j], acc[i * 8 + j + 1],
                                   acc[i * 8 + j + 2], acc[i * 8 + j + 3]);
            *reinterpret_cast<float4*>(crow + j) = v;
        }
    }
}

// ---------------------------------------------------------------------------
// s_self / s_neigh: one warp per (h,b,n) row; dual dot over k=1024
// ---------------------------------------------------------------------------
__global__ __launch_bounds__(256) void s_kernel(const float* __restrict__ a_self,
                                                const float* __restrict__ a_neigh) {
    const int warp = blockIdx.x * 8 + (threadIdx.x >> 5);
    const int lane = threadIdx.x & 31;
    if (warp >= H * BATCH * NN) return;
    const int h = warp >> 14;  // / (BATCH*NN)

    const float4* frow = reinterpret_cast<const float4*>(g_feats + (size_t)warp * FK);
    const float4* as   = reinterpret_cast<const float4*>(a_self + h * FK);
    const float4* an   = reinterpret_cast<const float4*>(a_neigh + h * FK);

    float s0 = 0.f, s1 = 0.f;
#pragma unroll
    for (int i = lane; i < FK / 4; i += 32) {
        float4 f = frow[i];
        float4 u = as[i];
        float4 v = an[i];
        s0 += f.x * u.x + f.y * u.y + f.z * u.z + f.w * u.w;
        s1 += f.x * v.x + f.y * v.y + f.z * v.z + f.w * v.w;
    }
#pragma unroll
    for (int o = 16; o; o >>= 1) {
        s0 += __shfl_xor_sync(0xFFFFFFFFu, s0, o);
        s1 += __shfl_xor_sync(0xFFFFFFFFu, s1, o);
    }
    if (lane == 0) {
        g_sself[warp]  = s0;
        g_sneigh[warp] = s1;
    }
}

// ---------------------------------------------------------------------------
// softmax row kernel: attn[h,b,i,:] = softmax_j(leaky(s_self[i] + s_neigh[j]))
// one 256-thread block per row; writes directly into the output slab.
// ---------------------------------------------------------------------------
__global__ __launch_bounds__(256) void softmax_kernel(float* __restrict__ out) {
    const int r  = blockIdx.x;        // (h*16+b)*1024 + i
    const int hb = r >> 10;
    const int tid = threadIdx.x;

    const float  si = g_sself[r];
    const float* sn = g_sneigh + (size_t)hb * NN;

    __shared__ float redmax[8];
    __shared__ float redsum[8];
    __shared__ float bmax, bsum;

    float lv[4];
    float m = -1e30f;
#pragma unroll
    for (int jj = 0; jj < 4; jj++) {
        const int j = tid + jj * 256;
        float v = si + sn[j];
        v = (v >= 0.f) ? v : 0.2f * v;
        lv[jj] = v;
        m = fmaxf(m, v);
    }
#pragma unroll
    for (int o = 16; o; o >>= 1) m = fmaxf(m, __shfl_xor_sync(0xFFFFFFFFu, m, o));
    if ((tid & 31) == 0) redmax[tid >> 5] = m;
    __syncthreads();
    if (tid == 0) {
        float t = redmax[0];
#pragma unroll
        for (int i = 1; i < 8; i++) t = fmaxf(t, redmax[i]);
        bmax = t;
    }
    __syncthreads();
    m = bmax;

    float sum = 0.f;
#pragma unroll
    for (int jj = 0; jj < 4; jj++) {
        lv[jj] = __expf(lv[jj] - m);
        sum += lv[jj];
    }
#pragma unroll
    for (int o = 16; o; o >>= 1) sum += __shfl_xor_sync(0xFFFFFFFFu, sum, o);
    if ((tid & 31) == 0) redsum[tid >> 5] = sum;
    __syncthreads();
    if (tid == 0) {
        float t = 0.f;
#pragma unroll
        for (int i = 0; i < 8; i++) t += redsum[i];
        bsum = t;
    }
    __syncthreads();
    const float inv = 1.f / bsum;

    float* orow = out + ((size_t)hb << 20) + ((size_t)(r & 1023) << 10);
#pragma unroll
    for (int jj = 0; jj < 4; jj++) orow[tid + jj * 256] = lv[jj] * inv;
}

// ---------------------------------------------------------------------------
// GEMM2: out[b] = (1/3) * sum_h attn[h,b] (1024x1024) @ feats[h,b] (1024x1024)
//                 + mean_h bias[h]
// same 128x128x8 tiling; K loop runs over 3 heads x 1024.
// attn is read back from the output buffer (written by softmax_kernel).
// ---------------------------------------------------------------------------
__global__ __launch_bounds__(256) void gemm2_kernel(const float* __restrict__ outbuf,
                                                    const float* __restrict__ biases,
                                                    float* __restrict__ out) {
    const int b    = blockIdx.z;
    const int cRow = blockIdx.y;   // 0..7
    const int cCol = blockIdx.x;   // 0..7

    __shared__ float As[8 * 128];
    __shared__ float Bs[8 * 128];

    const int tid       = threadIdx.x;
    const int threadCol = tid & 15;
    const int threadRow = tid >> 4;
    const int innerRowA = tid >> 1;
    const int innerColA = tid & 1;
    const int innerRowB = tid >> 5;
    const int innerColB = tid & 31;

    float acc[64];
#pragma unroll
    for (int i = 0; i < 64; i++) acc[i] = 0.f;
    float regM[8], regN[8];

    for (int h = 0; h < H; h++) {
        const float* A = outbuf + (((size_t)h * BATCH + b) << 20) + (size_t)cRow * 128 * NN;
        const float* B = g_feats + (((size_t)h * BATCH + b) << 20) + (size_t)cCol * 128;
        for (int bk = 0; bk < NN; bk += 8) {
            float4 a4 = *reinterpret_cast<const float4*>(A + (size_t)innerRowA * NN + innerColA * 4);
            As[(innerColA * 4 + 0) * 128 + innerRowA] = a4.x;
            As[(innerColA * 4 + 1) * 128 + innerRowA] = a4.y;
            As[(innerColA * 4 + 2) * 128 + innerRowA] = a4.z;
            As[(innerColA * 4 + 3) * 128 + innerRowA] = a4.w;
            *reinterpret_cast<float4*>(&Bs[innerRowB * 128 + innerColB * 4]) =
                *reinterpret_cast<const float4*>(B + (size_t)innerRowB * FK + innerColB * 4);
            __syncthreads();
            A += 8;
            B += (size_t)8 * FK;
#pragma unroll
            for (int k = 0; k < 8; k++) {
                *reinterpret_cast<float4*>(&regM[0]) = *reinterpret_cast<float4*>(&As[k * 128 + threadRow * 8]);
                *reinterpret_cast<float4*>(&regM[4]) = *reinterpret_cast<float4*>(&As[k * 128 + threadRow * 8 + 4]);
                *reinterpret_cast<float4*>(&regN[0]) = *reinterpret_cast<float4*>(&Bs[k * 128 + threadCol * 8]);
                *reinterpret_cast<float4*>(&regN[4]) = *reinterpret_cast<float4*>(&Bs[k * 128 + threadCol * 8 + 4]);
#pragma unroll
                for (int i = 0; i < 8; i++)
#pragma unroll
                    for (int j = 0; j < 8; j++) acc[i * 8 + j] += regM[i] * regN[j];
            }
            __syncthreads();
        }
    }

    // epilogue: mean over heads + mean bias
    const float inv3 = 1.f / 3.f;
    float bm[8];
#pragma unroll
    for (int j = 0; j < 8; j++) {
        const int col = cCol * 128 + threadCol * 8 + j;
        bm[j] = (biases[col] + biases[FK + col] + biases[2 * FK + col]) * inv3;
    }
    float* C = out + (((size_t)(H * BATCH) + b) << 20) + (size_t)cRow * 128 * FK + (size_t)cCol * 128;
#pragma unroll
    for (int i = 0; i < 8; i++) {
        float* crow = C + (size_t)(threadRow * 8 + i) * FK + threadCol * 8;
#pragma unroll
        for (int j = 0; j < 8; j += 4) {
            float4 v = make_float4(acc[i * 8 + j] * inv3 + bm[j],
                                   acc[i * 8 + j + 1] * inv3 + bm[j + 1],
                                   acc[i * 8 + j + 2] * inv3 + bm[j + 2],
                                   acc[i * 8 + j + 3] * inv3 + bm[j + 3]);
            *reinterpret_cast<float4*>(crow + j) = v;
        }
    }
}

// ---------------------------------------------------------------------------
extern "C" void kernel_launch(void* const* d_in, const int* in_sizes, int n_in,
                              void* d_out, int out_size) {
    const float* x        = (const float*)d_in[0];
    const float* kernels  = (const float*)d_in[1];
    const float* biases   = (const float*)d_in[2];
    const float* a_self   = (const float*)d_in[3];
    const float* a_neigh  = (const float*)d_in[4];
    float* out = (float*)d_out;

    dim3 g1(FK / 128, M1 / 128, H);      // (8, 128, 3)
    gemm1_kernel<<<g1, 256>>>(x, kernels);

    s_kernel<<<(H * BATCH * NN) / 8, 256>>>(a_self, a_neigh);

    softmax_kernel<<<H * BATCH * NN, 256>>>(out);

    dim3 g2(FK / 128, NN / 128, BATCH);  // (8, 8, 16)
    gemm2_kernel<<<g2, 256>>>(out, biases, out);
}

// round 5
// speedup vs baseline: 2.5767x; 2.5767x over previous
#include <cuda_runtime.h>
#include <cuda_bf16.h>
#include <cstdint>

#define H 3
#define BATCH 16
#define NN 1024
#define FF 512
#define FK 1024
#define M1 (BATCH * NN)

// ---------------------------------------------------------------------------
// scratch (static device allocations; ~440 MB)
// ---------------------------------------------------------------------------
__device__ __align__(16) __nv_bfloat16 g_xhi[(size_t)M1 * FF];
__device__ __align__(16) __nv_bfloat16 g_xlo[(size_t)M1 * FF];
__device__ __align__(16) __nv_bfloat16 g_whi[(size_t)H * FF * FK];          // [h][f][k]
__device__ __align__(16) __nv_bfloat16 g_wlo[(size_t)H * FF * FK];
__device__ __align__(16) __nv_bfloat16 g_fhi[(size_t)H * BATCH * NN * FK];  // [h][b][n][k]
__device__ __align__(16) __nv_bfloat16 g_flo[(size_t)H * BATCH * NN * FK];
__device__ __align__(16) __nv_bfloat16 g_athi[(size_t)H * BATCH * NN * NN]; // [h][b][n][m]
__device__ __align__(16) __nv_bfloat16 g_atlo[(size_t)H * BATCH * NN * NN];
__device__ float g_sself[H * BATCH * NN];
__device__ float g_sneigh[H * BATCH * NN];

// ---------------------------------------------------------------------------
// PTX helpers (plain compute_103-legal: cp.async / ldmatrix / mma.sync)
// ---------------------------------------------------------------------------
__device__ __forceinline__ uint32_t smem_u32(const void* p) {
    uint32_t a;
    asm("{ .reg .u64 t; cvta.to.shared.u64 t, %1; cvt.u32.u64 %0, t; }" : "=r"(a) : "l"(p));
    return a;
}
__device__ __forceinline__ void cpa16(uint32_t dst, const void* src) {
    asm volatile("cp.async.cg.shared.global [%0], [%1], 16;" :: "r"(dst), "l"(src));
}
#define CP_COMMIT() asm volatile("cp.async.commit_group;" ::: "memory")

__device__ __forceinline__ void ldsm4(uint32_t r[4], uint32_t addr) {
    asm volatile("ldmatrix.sync.aligned.m8n8.x4.shared.b16 {%0,%1,%2,%3}, [%4];"
                 : "=r"(r[0]), "=r"(r[1]), "=r"(r[2]), "=r"(r[3]) : "r"(addr));
}
__device__ __forceinline__ void ldsm4t(uint32_t r[4], uint32_t addr) {
    asm volatile("ldmatrix.sync.aligned.m8n8.x4.trans.shared.b16 {%0,%1,%2,%3}, [%4];"
                 : "=r"(r[0]), "=r"(r[1]), "=r"(r[2]), "=r"(r[3]) : "r"(addr));
}
__device__ __forceinline__ void mma16816(float c[4], const uint32_t a[4],
                                         uint32_t b0, uint32_t b1) {
    asm volatile(
        "mma.sync.aligned.m16n8k16.row.col.f32.bf16.bf16.f32 "
        "{%0,%1,%2,%3}, {%4,%5,%6,%7}, {%8,%9}, {%0,%1,%2,%3};"
        : "+f"(c[0]), "+f"(c[1]), "+f"(c[2]), "+f"(c[3])
        : "r"(a[0]), "r"(a[1]), "r"(a[2]), "r"(a[3]), "r"(b0), "r"(b1));
}

__device__ __forceinline__ uint32_t pack_bf16x2(float a, float b) {
    const unsigned short ha = __bfloat16_as_ushort(__float2bfloat16(a));
    const unsigned short hb = __bfloat16_as_ushort(__float2bfloat16(b));
    return (uint32_t)ha | ((uint32_t)hb << 16);
}
__device__ __forceinline__ float2 bf2f(uint32_t w) {
    __nv_bfloat162 t = *reinterpret_cast<__nv_bfloat162*>(&w);
    return __bfloat1622float2(t);
}

// ---------------------------------------------------------------------------
// smem layout: 3-stage pipeline, per stage: Ah/Al 128x32 (pad80B), Bh/Bl 32x128 (pad272B)
// ---------------------------------------------------------------------------
#define A_STRIDE 80
#define B_STRIDE 272
#define OFF_AH 0
#define OFF_AL 10240
#define OFF_BH 20480
#define OFF_BL 29184
#define STAGE_BYTES 37888
#define NSTAGE 3
#define SMEM_BYTES (STAGE_BYTES * NSTAGE)   // 113664

__device__ __forceinline__ void load_chunk(uint32_t sst, int tid,
                                           const __nv_bfloat16* __restrict__ ah,
                                           const __nv_bfloat16* __restrict__ al,
                                           const __nv_bfloat16* __restrict__ bh,
                                           const __nv_bfloat16* __restrict__ bl,
                                           int lda, int ldb) {
#pragma unroll
    for (int i = 0; i < 2; i++) {
        const int u = tid + 256 * i;
        const int row = u >> 2, seg = u & 3;
        cpa16(sst + OFF_AH + row * A_STRIDE + seg * 16, ah + (size_t)row * lda + seg * 8);
        cpa16(sst + OFF_AL + row * A_STRIDE + seg * 16, al + (size_t)row * lda + seg * 8);
    }
#pragma unroll
    for (int i = 0; i < 2; i++) {
        const int u = tid + 256 * i;
        const int row = u >> 4, seg = u & 15;
        cpa16(sst + OFF_BH + row * B_STRIDE + seg * 16, bh + (size_t)row * ldb + seg * 8);
        cpa16(sst + OFF_BL + row * B_STRIDE + seg * 16, bl + (size_t)row * ldb + seg * 8);
    }
    CP_COMMIT();
}

// compute one K=32 chunk: acc += Ah*Bh + Ah*Bl + Al*Bh
__device__ __forceinline__ void compute_chunk(uint32_t sst, int lane, int wm, int wn,
                                              float acc[4][4][4]) {
#pragma unroll
    for (int kk = 0; kk < 32; kk += 16) {
        uint32_t Ah[4][4], Al[4][4], Bh[2][4], Bl[2][4];
        const uint32_t arow = wm * 64 + (lane & 7) + ((lane >> 3) & 1) * 8;
        const uint32_t acoff = (kk + (lane >> 4) * 8) * 2;
#pragma unroll
        for (int mi = 0; mi < 4; mi++) {
            const uint32_t ad = sst + OFF_AH + (arow + mi * 16) * A_STRIDE + acoff;
            ldsm4(Ah[mi], ad);
            ldsm4(Al[mi], ad + (OFF_AL - OFF_AH));
        }
        const uint32_t brow = kk + ((lane >> 3) & 1) * 8 + (lane & 7);
        const uint32_t bcoff = (wn * 32 + (lane >> 4) * 8) * 2;
#pragma unroll
        for (int np = 0; np < 2; np++) {
            const uint32_t bd = sst + OFF_BH + brow * B_STRIDE + bcoff + np * 32;
            ldsm4t(Bh[np], bd);
            ldsm4t(Bl[np], bd + (OFF_BL - OFF_BH));
        }
#pragma unroll
        for (int mi = 0; mi < 4; mi++)
#pragma unroll
            for (int ni = 0; ni < 4; ni++)
                mma16816(acc[mi][ni], Ah[mi], Bh[ni >> 1][(ni & 1) * 2], Bh[ni >> 1][(ni & 1) * 2 + 1]);
#pragma unroll
        for (int mi = 0; mi < 4; mi++)
#pragma unroll
            for (int ni = 0; ni < 4; ni++)
                mma16816(acc[mi][ni], Ah[mi], Bl[ni >> 1][(ni & 1) * 2], Bl[ni >> 1][(ni & 1) * 2 + 1]);
#pragma unroll
        for (int mi = 0; mi < 4; mi++)
#pragma unroll
            for (int ni = 0; ni < 4; ni++)
                mma16816(acc[mi][ni], Al[mi], Bh[ni >> 1][(ni & 1) * 2], Bh[ni >> 1][(ni & 1) * 2 + 1]);
    }
}

// ---------------------------------------------------------------------------
// GEMM1: feats[h] = X (16384x512) @ W[h] (512x1024); stores bf16 hi/lo feats
// ---------------------------------------------------------------------------
__global__ __launch_bounds__(256, 1) void gemm1_mma() {
    extern __shared__ char smem[];
    const int tid = threadIdx.x, lane = tid & 31, wid = tid >> 5;
    const int wm = wid >> 2, wn = wid & 3;
    const uint32_t sb = smem_u32(smem);
    const int cT = blockIdx.x, rT = blockIdx.y, h = blockIdx.z;

    const __nv_bfloat16* Ah = g_xhi + (size_t)rT * 128 * FF;
    const __nv_bfloat16* Al = g_xlo + (size_t)rT * 128 * FF;
    const __nv_bfloat16* Bh = g_whi + (size_t)h * FF * FK + (size_t)cT * 128;
    const __nv_bfloat16* Bl = g_wlo + (size_t)h * FF * FK + (size_t)cT * 128;

    float acc[4][4][4];
#pragma unroll
    for (int i = 0; i < 4; i++)
#pragma unroll
        for (int j = 0; j < 4; j++)
#pragma unroll
            for (int k = 0; k < 4; k++) acc[i][j][k] = 0.f;

    const int NC = FF / 32;  // 16
    load_chunk(sb, tid, Ah, Al, Bh, Bl, FF, FK);
    load_chunk(sb + STAGE_BYTES, tid, Ah + 32, Al + 32,
               Bh + (size_t)32 * FK, Bl + (size_t)32 * FK, FF, FK);

    for (int c = 0; c < NC; c++) {
        if (c < NC - 1) asm volatile("cp.async.wait_group 1;" ::: "memory");
        else            asm volatile("cp.async.wait_group 0;" ::: "memory");
        __syncthreads();
        if (c + 2 < NC) {
            const int cn = c + 2;
            load_chunk(sb + (cn % 3) * STAGE_BYTES, tid,
                       Ah + cn * 32, Al + cn * 32,
                       Bh + (size_t)(cn * 32) * FK, Bl + (size_t)(cn * 32) * FK, FF, FK);
        }
        compute_chunk(sb + (c % 3) * STAGE_BYTES, lane, wm, wn, acc);
        __syncthreads();
    }

    // epilogue: write bf16 hi/lo feats in natural layout [h][b][n][k]
    const int b = rT >> 3;
    const size_t fbase = ((size_t)(h * BATCH + b) << 20);
    const int nrow0 = (rT & 7) * 128;
#pragma unroll
    for (int mi = 0; mi < 4; mi++)
#pragma unroll
        for (int ni = 0; ni < 4; ni++) {
            const int row0 = wm * 64 + mi * 16 + (lane >> 2);
            const int col0 = cT * 128 + wn * 32 + ni * 8 + (lane & 3) * 2;
#pragma unroll
            for (int half = 0; half < 2; half++) {
                const int n = nrow0 + row0 + half * 8;
                const float v0 = acc[mi][ni][half * 2];
                const float v1 = acc[mi][ni][half * 2 + 1];
                const uint32_t ph = pack_bf16x2(v0, v1);
                const float2 hf = bf2f(ph);
                const uint32_t pl = pack_bf16x2(v0 - hf.x, v1 - hf.y);
                const size_t off = fbase + (size_t)n * FK + col0;
                *reinterpret_cast<uint32_t*>(g_fhi + off) = ph;
                *reinterpret_cast<uint32_t*>(g_flo + off) = pl;
            }
        }
}

// ---------------------------------------------------------------------------
// GEMM2: out[b] = (1/3) sum_h attn[h,b] @ feats[h,b] + mean bias ; K = 3*1024
// ---------------------------------------------------------------------------
__global__ __launch_bounds__(256, 1) void gemm2_mma(const float* __restrict__ biases,
                                                    float* __restrict__ out) {
    extern __shared__ char smem[];
    const int tid = threadIdx.x, lane = tid & 31, wid = tid >> 5;
    const int wm = wid >> 2, wn = wid & 3;
    const uint32_t sb = smem_u32(smem);
    const int cT = blockIdx.x, nT = blockIdx.y, b = blockIdx.z;

    float acc[4][4][4];
#pragma unroll
    for (int i = 0; i < 4; i++)
#pragma unroll
        for (int j = 0; j < 4; j++)
#pragma unroll
            for (int k = 0; k < 4; k++) acc[i][j][k] = 0.f;

    const int NC = 96;
    auto issue = [&](int cn) {
        const int hh = cn >> 5, kc = cn & 31;
        const size_t hb = ((size_t)(hh * BATCH + b)) << 20;
        load_chunk(sb + (cn % 3) * STAGE_BYTES, tid,
                   g_athi + hb + ((size_t)nT << 17) + kc * 32,
                   g_atlo + hb + ((size_t)nT << 17) + kc * 32,
                   g_fhi + hb + ((size_t)(kc * 32) << 10) + cT * 128,
                   g_flo + hb + ((size_t)(kc * 32) << 10) + cT * 128, NN, FK);
    };
    issue(0);
    issue(1);

    for (int c = 0; c < NC; c++) {
        if (c < NC - 1) asm volatile("cp.async.wait_group 1;" ::: "memory");
        else            asm volatile("cp.async.wait_group 0;" ::: "memory");
        __syncthreads();
        if (c + 2 < NC) issue(c + 2);
        compute_chunk(sb + (c % 3) * STAGE_BYTES, lane, wm, wn, acc);
        __syncthreads();
    }

    const float inv3 = 1.f / 3.f;
    const size_t obase = ((size_t)(H * BATCH + b) << 20) + ((size_t)nT << 17);
#pragma unroll
    for (int mi = 0; mi < 4; mi++)
#pragma unroll
        for (int ni = 0; ni < 4; ni++) {
            const int row0 = wm * 64 + mi * 16 + (lane >> 2);
            const int col0 = cT * 128 + wn * 32 + ni * 8 + (lane & 3) * 2;
            const float bm0 = (biases[col0] + biases[FK + col0] + biases[2 * FK + col0]) * inv3;
            const float bm1 = (biases[col0 + 1] + biases[FK + col0 + 1] + biases[2 * FK + col0 + 1]) * inv3;
#pragma unroll
            for (int half = 0; half < 2; half++) {
                const int n = row0 + half * 8;
                float2 v;
                v.x = acc[mi][ni][half * 2] * inv3 + bm0;
                v.y = acc[mi][ni][half * 2 + 1] * inv3 + bm1;
                *reinterpret_cast<float2*>(out + obase + (size_t)n * FK + col0) = v;
            }
        }
}

// ---------------------------------------------------------------------------
// prep: bf16 hi/lo splits (natural layouts)
// ---------------------------------------------------------------------------
__global__ __launch_bounds__(1024) void split_x(const float* __restrict__ x) {
    const size_t i = (size_t)blockIdx.x * 1024 + threadIdx.x;
    const float v = x[i];
    const __nv_bfloat16 hv = __float2bfloat16(v);
    g_xhi[i] = hv;
    g_xlo[i] = __float2bfloat16(v - __bfloat162float(hv));
}
__global__ __launch_bounds__(1024) void split_w(const float* __restrict__ w) {
    const size_t i = (size_t)blockIdx.x * 1024 + threadIdx.x;
    const float v = w[i];
    const __nv_bfloat16 hv = __float2bfloat16(v);
    g_whi[i] = hv;
    g_wlo[i] = __float2bfloat16(v - __bfloat162float(hv));
}

// ---------------------------------------------------------------------------
// s_self / s_neigh: one warp per (h,b,n) row; dual dot over k=1024 (hi+lo)
// ---------------------------------------------------------------------------
__global__ __launch_bounds__(256) void s_kernel(const float* __restrict__ a_self,
                                                const float* __restrict__ a_neigh) {
    const int r = blockIdx.x * 8 + (threadIdx.x >> 5);
    const int lane = threadIdx.x & 31;
    const int h = r >> 14;

    const uint4* fh = reinterpret_cast<const uint4*>(g_fhi + ((size_t)r << 10));
    const uint4* fl = reinterpret_cast<const uint4*>(g_flo + ((size_t)r << 10));
    const float4* as4 = reinterpret_cast<const float4*>(a_self + h * FK);
    const float4* an4 = reinterpret_cast<const float4*>(a_neigh + h * FK);

    float s0 = 0.f, s1 = 0.f;
#pragma unroll
    for (int i = lane; i < 128; i += 32) {
        const uint4 uh = fh[i];
        const uint4 ul = fl[i];
        const uint32_t* ph = reinterpret_cast<const uint32_t*>(&uh);
        const uint32_t* pl = reinterpret_cast<const uint32_t*>(&ul);
#pragma unroll
        for (int e = 0; e < 2; e++) {
            const float4 a = as4[i * 2 + e];
            const float4 nq = an4[i * 2 + e];
            const float2 h0 = bf2f(ph[e * 2]), l0 = bf2f(pl[e * 2]);
            const float2 h1 = bf2f(ph[e * 2 + 1]), l1 = bf2f(pl[e * 2 + 1]);
            const float f0 = h0.x + l0.x, f1 = h0.y + l0.y;
            const float f2 = h1.x + l1.x, f3 = h1.y + l1.y;
            s0 += f0 * a.x + f1 * a.y + f2 * a.z + f3 * a.w;
            s1 += f0 * nq.x + f1 * nq.y + f2 * nq.z + f3 * nq.w;
        }
    }
#pragma unroll
    for (int o = 16; o; o >>= 1) {
        s0 += __shfl_xor_sync(0xFFFFFFFFu, s0, o);
        s1 += __shfl_xor_sync(0xFFFFFFFFu, s1, o);
    }
    if (lane == 0) {
        g_sself[r] = s0;
        g_sneigh[r] = s1;
    }
}

// ---------------------------------------------------------------------------
// softmax row kernel: fp32 attn into out slab + bf16 hi/lo copies for GEMM2
// ---------------------------------------------------------------------------
__global__ __launch_bounds__(256) void softmax_kernel(float* __restrict__ out) {
    const int r = blockIdx.x;
    const int hb = r >> 10;
    const int tid = threadIdx.x;

    const float si = g_sself[r];
    const float* sn = g_sneigh + (size_t)hb * NN;

    __shared__ float redmax[8], redsum[8];
    __shared__ float bmax, bsum;

    float lv[4];
    float m = -1e30f;
#pragma unroll
    for (int jj = 0; jj < 4; jj++) {
        const int j = tid + jj * 256;
        float v = si + sn[j];
        v = (v >= 0.f) ? v : 0.2f * v;
        lv[jj] = v;
        m = fmaxf(m, v);
    }
#pragma unroll
    for (int o = 16; o; o >>= 1) m = fmaxf(m, __shfl_xor_sync(0xFFFFFFFFu, m, o));
    if ((tid & 31) == 0) redmax[tid >> 5] = m;
    __syncthreads();
    if (tid == 0) {
        float t = redmax[0];
#pragma unroll
        for (int i = 1; i < 8; i++) t = fmaxf(t, redmax[i]);
        bmax = t;
    }
    __syncthreads();
    m = bmax;

    float sum = 0.f;
#pragma unroll
    for (int jj = 0; jj < 4; jj++) {
        lv[jj] = __expf(lv[jj] - m);
        sum += lv[jj];
    }
#pragma unroll
    for (int o = 16; o; o >>= 1) sum += __shfl_xor_sync(0xFFFFFFFFu, sum, o);
    if ((tid & 31) == 0) redsum[tid >> 5] = sum;
    __syncthreads();
    if (tid == 0) {
        float t = 0.f;
#pragma unroll
        for (int i = 0; i < 8; i++) t += redsum[i];
        bsum = t;
    }
    __syncthreads();
    const float inv = 1.f / bsum;

    const size_t rowoff = ((size_t)hb << 20) + ((size_t)(r & 1023) << 10);
    float* orow = out + rowoff;
#pragma unroll
    for (int jj = 0; jj < 4; jj++) {
        const int j = tid + jj * 256;
        const float p = lv[jj] * inv;
        orow[j] = p;
        const __nv_bfloat16 ph = __float2bfloat16(p);
        g_athi[rowoff + j] = ph;
        g_atlo[rowoff + j] = __float2bfloat16(p - __bfloat162float(ph));
    }
}

// ---------------------------------------------------------------------------
extern "C" void kernel_launch(void* const* d_in, const int* in_sizes, int n_in,
                              void* d_out, int out_size) {
    const float* x       = (const float*)d_in[0];
    const float* kernels = (const float*)d_in[1];
    const float* biases  = (const float*)d_in[2];
    const float* a_self  = (const float*)d_in[3];
    const float* a_neigh = (const float*)d_in[4];
    float* out = (float*)d_out;

    static bool attr_set = false;
    if (!attr_set) {
        cudaFuncSetAttribute(gemm1_mma, cudaFuncAttributeMaxDynamicSharedMemorySize, SMEM_BYTES);
        cudaFuncSetAttribute(gemm2_mma, cudaFuncAttributeMaxDynamicSharedMemorySize, SMEM_BYTES);
        attr_set = true;
    }

    split_x<<<(M1 * FF) / 1024, 1024>>>(x);
    split_w<<<(H * FF * FK) / 1024, 1024>>>(kernels);

    gemm1_mma<<<dim3(FK / 128, M1 / 128, H), 256, SMEM_BYTES>>>();

    s_kernel<<<(H * BATCH * NN) / 8, 256>>>(a_self, a_neigh);

    softmax_kernel<<<H * BATCH * NN, 256>>>(out);

    gemm2_mma<<<dim3(FK / 128, NN / 128, BATCH), 256, SMEM_BYTES>>>(biases, out);
}

// round 6
// speedup vs baseline: 2.9889x; 1.1600x over previous
#include <cuda_runtime.h>
#include <cuda_fp16.h>
#include <cstdint>

#define H 3
#define BATCH 16
#define NN 1024
#define FF 512
#define FK 1024
#define M1 (BATCH * NN)

// ---------------------------------------------------------------------------
// scratch (static device allocations)
// ---------------------------------------------------------------------------
__device__ __align__(16) __half g_xhi[(size_t)M1 * FF];
__device__ __align__(16) __half g_xlo[(size_t)M1 * FF];
__device__ __align__(16) __half g_whi[(size_t)H * FF * FK];          // [h][f][k]
__device__ __align__(16) __half g_wlo[(size_t)H * FF * FK];
__device__ __align__(16) __half g_fhi[(size_t)H * BATCH * NN * FK];  // [h][b][n][k]
__device__ __align__(16) __half g_flo[(size_t)H * BATCH * NN * FK];
__device__ __align__(16) __half g_ath[(size_t)H * BATCH * NN * NN];  // [h][b][n][m] fp16
__device__ float g_sself[H * BATCH * NN];
__device__ float g_sneigh[H * BATCH * NN];

// ---------------------------------------------------------------------------
// PTX helpers (plain compute_103-legal: cp.async / ldmatrix / mma.sync fp16)
// ---------------------------------------------------------------------------
__device__ __forceinline__ uint32_t smem_u32(const void* p) {
    uint32_t a;
    asm("{ .reg .u64 t; cvta.to.shared.u64 t, %1; cvt.u32.u64 %0, t; }" : "=r"(a) : "l"(p));
    return a;
}
__device__ __forceinline__ void cpa16(uint32_t dst, const void* src) {
    asm volatile("cp.async.cg.shared.global [%0], [%1], 16;" :: "r"(dst), "l"(src));
}
#define CP_COMMIT() asm volatile("cp.async.commit_group;" ::: "memory")

__device__ __forceinline__ void ldsm4(uint32_t r[4], uint32_t addr) {
    asm volatile("ldmatrix.sync.aligned.m8n8.x4.shared.b16 {%0,%1,%2,%3}, [%4];"
                 : "=r"(r[0]), "=r"(r[1]), "=r"(r[2]), "=r"(r[3]) : "r"(addr));
}
__device__ __forceinline__ void ldsm4t(uint32_t r[4], uint32_t addr) {
    asm volatile("ldmatrix.sync.aligned.m8n8.x4.trans.shared.b16 {%0,%1,%2,%3}, [%4];"
                 : "=r"(r[0]), "=r"(r[1]), "=r"(r[2]), "=r"(r[3]) : "r"(addr));
}
__device__ __forceinline__ void mma16816(float c[4], const uint32_t a[4],
                                         uint32_t b0, uint32_t b1) {
    asm volatile(
        "mma.sync.aligned.m16n8k16.row.col.f32.f16.f16.f32 "
        "{%0,%1,%2,%3}, {%4,%5,%6,%7}, {%8,%9}, {%0,%1,%2,%3};"
        : "+f"(c[0]), "+f"(c[1]), "+f"(c[2]), "+f"(c[3])
        : "r"(a[0]), "r"(a[1]), "r"(a[2]), "r"(a[3]), "r"(b0), "r"(b1));
}

__device__ __forceinline__ uint32_t pack_h2(float a, float b) {
    __half2 t = __floats2half2_rn(a, b);
    return *reinterpret_cast<uint32_t*>(&t);
}
__device__ __forceinline__ float2 h2f2(uint32_t w) {
    __half2 t = *reinterpret_cast<__half2*>(&w);
    return __half22float2(t);
}

// ---------------------------------------------------------------------------
// smem layout: 3-stage pipeline; per stage: A/AL 128x32 (pad 80B), B hi/lo 32x128 (pad 272B)
// ---------------------------------------------------------------------------
#define A_STRIDE 80
#define B_STRIDE 272
#define OFF_AH 0
#define OFF_AL 10240
#define OFF_BH 20480
#define OFF_BL 29184
#define STAGE_BYTES 37888
#define SMEM_BYTES (STAGE_BYTES * 3)   // 113664

// gemm1: A hi/lo + B hi/lo (4 arrays)
__device__ __forceinline__ void load_chunk4(uint32_t sst, int tid,
                                            const __half* __restrict__ ah,
                                            const __half* __restrict__ al,
                                            const __half* __restrict__ bh,
                                            const __half* __restrict__ bl,
                                            int lda, int ldb) {
#pragma unroll
    for (int i = 0; i < 2; i++) {
        const int u = tid + 256 * i;
        const int row = u >> 2, seg = u & 3;
        cpa16(sst + OFF_AH + row * A_STRIDE + seg * 16, ah + (size_t)row * lda + seg * 8);
        cpa16(sst + OFF_AL + row * A_STRIDE + seg * 16, al + (size_t)row * lda + seg * 8);
    }
#pragma unroll
    for (int i = 0; i < 2; i++) {
        const int u = tid + 256 * i;
        const int row = u >> 4, seg = u & 15;
        cpa16(sst + OFF_BH + row * B_STRIDE + seg * 16, bh + (size_t)row * ldb + seg * 8);
        cpa16(sst + OFF_BL + row * B_STRIDE + seg * 16, bl + (size_t)row * ldb + seg * 8);
    }
    CP_COMMIT();
}

// gemm2: A single + B hi/lo (3 arrays)
__device__ __forceinline__ void load_chunk3(uint32_t sst, int tid,
                                            const __half* __restrict__ a,
                                            const __half* __restrict__ bh,
                                            const __half* __restrict__ bl,
                                            int lda, int ldb) {
#pragma unroll
    for (int i = 0; i < 2; i++) {
        const int u = tid + 256 * i;
        const int row = u >> 2, seg = u & 3;
        cpa16(sst + OFF_AH + row * A_STRIDE + seg * 16, a + (size_t)row * lda + seg * 8);
    }
#pragma unroll
    for (int i = 0; i < 2; i++) {
        const int u = tid + 256 * i;
        const int row = u >> 4, seg = u & 15;
        cpa16(sst + OFF_BH + row * B_STRIDE + seg * 16, bh + (size_t)row * ldb + seg * 8);
        cpa16(sst + OFF_BL + row * B_STRIDE + seg * 16, bl + (size_t)row * ldb + seg * 8);
    }
    CP_COMMIT();
}

// gemm1 chunk: acc += Ah*Bh + Ah*Bl + Al*Bh
__device__ __forceinline__ void compute_chunk_g1(uint32_t sst, int lane, int wm, int wn,
                                                 float acc[4][4][4]) {
#pragma unroll
    for (int kk = 0; kk < 32; kk += 16) {
        uint32_t Ah[4][4], Al[4][4], Bh[2][4], Bl[2][4];
        const uint32_t arow = wm * 64 + (lane & 7) + ((lane >> 3) & 1) * 8;
        const uint32_t acoff = (kk + (lane >> 4) * 8) * 2;
#pragma unroll
        for (int mi = 0; mi < 4; mi++) {
            const uint32_t ad = sst + OFF_AH + (arow + mi * 16) * A_STRIDE + acoff;
            ldsm4(Ah[mi], ad);
            ldsm4(Al[mi], ad + (OFF_AL - OFF_AH));
        }
        const uint32_t brow = kk + ((lane >> 3) & 1) * 8 + (lane & 7);
        const uint32_t bcoff = (wn * 32 + (lane >> 4) * 8) * 2;
#pragma unroll
        for (int np = 0; np < 2; np++) {
            const uint32_t bd = sst + OFF_BH + brow * B_STRIDE + bcoff + np * 32;
            ldsm4t(Bh[np], bd);
            ldsm4t(Bl[np], bd + (OFF_BL - OFF_BH));
        }
#pragma unroll
        for (int mi = 0; mi < 4; mi++)
#pragma unroll
            for (int ni = 0; ni < 4; ni++)
                mma16816(acc[mi][ni], Ah[mi], Bh[ni >> 1][(ni & 1) * 2], Bh[ni >> 1][(ni & 1) * 2 + 1]);
#pragma unroll
        for (int mi = 0; mi < 4; mi++)
#pragma unroll
            for (int ni = 0; ni < 4; ni++)
                mma16816(acc[mi][ni], Ah[mi], Bl[ni >> 1][(ni & 1) * 2], Bl[ni >> 1][(ni & 1) * 2 + 1]);
#pragma unroll
        for (int mi = 0; mi < 4; mi++)
#pragma unroll
            for (int ni = 0; ni < 4; ni++)
                mma16816(acc[mi][ni], Al[mi], Bh[ni >> 1][(ni & 1) * 2], Bh[ni >> 1][(ni & 1) * 2 + 1]);
    }
}

// gemm2 chunk: acc += A*Bh + A*Bl
__device__ __forceinline__ void compute_chunk_g2(uint32_t sst, int lane, int wm, int wn,
                                                 float acc[4][4][4]) {
#pragma unroll
    for (int kk = 0; kk < 32; kk += 16) {
        uint32_t A[4][4], Bh[2][4], Bl[2][4];
        const uint32_t arow = wm * 64 + (lane & 7) + ((lane >> 3) & 1) * 8;
        const uint32_t acoff = (kk + (lane >> 4) * 8) * 2;
#pragma unroll
        for (int mi = 0; mi < 4; mi++)
            ldsm4(A[mi], sst + OFF_AH + (arow + mi * 16) * A_STRIDE + acoff);
        const uint32_t brow = kk + ((lane >> 3) & 1) * 8 + (lane & 7);
        const uint32_t bcoff = (wn * 32 + (lane >> 4) * 8) * 2;
#pragma unroll
        for (int np = 0; np < 2; np++) {
            const uint32_t bd = sst + OFF_BH + brow * B_STRIDE + bcoff + np * 32;
            ldsm4t(Bh[np], bd);
            ldsm4t(Bl[np], bd + (OFF_BL - OFF_BH));
        }
#pragma unroll
        for (int mi = 0; mi < 4; mi++)
#pragma unroll
            for (int ni = 0; ni < 4; ni++)
                mma16816(acc[mi][ni], A[mi], Bh[ni >> 1][(ni & 1) * 2], Bh[ni >> 1][(ni & 1) * 2 + 1]);
#pragma unroll
        for (int mi = 0; mi < 4; mi++)
#pragma unroll
            for (int ni = 0; ni < 4; ni++)
                mma16816(acc[mi][ni], A[mi], Bl[ni >> 1][(ni & 1) * 2], Bl[ni >> 1][(ni & 1) * 2 + 1]);
    }
}

// ---------------------------------------------------------------------------
// GEMM1: feats[h] = X (16384x512) @ W[h] (512x1024); 3-pass; stores fp16 hi/lo
// ---------------------------------------------------------------------------
__global__ __launch_bounds__(256, 1) void gemm1_mma() {
    extern __shared__ char smem[];
    const int tid = threadIdx.x, lane = tid & 31, wid = tid >> 5;
    const int wm = wid >> 2, wn = wid & 3;
    const uint32_t sb = smem_u32(smem);
    const int cT = blockIdx.x, rT = blockIdx.y, h = blockIdx.z;

    const __half* Ah = g_xhi + (size_t)rT * 128 * FF;
    const __half* Al = g_xlo + (size_t)rT * 128 * FF;
    const __half* Bh = g_whi + (size_t)h * FF * FK + (size_t)cT * 128;
    const __half* Bl = g_wlo + (size_t)h * FF * FK + (size_t)cT * 128;

    float acc[4][4][4];
#pragma unroll
    for (int i = 0; i < 4; i++)
#pragma unroll
        for (int j = 0; j < 4; j++)
#pragma unroll
            for (int k = 0; k < 4; k++) acc[i][j][k] = 0.f;

    const int NC = FF / 32;  // 16
    load_chunk4(sb, tid, Ah, Al, Bh, Bl, FF, FK);
    load_chunk4(sb + STAGE_BYTES, tid, Ah + 32, Al + 32,
                Bh + (size_t)32 * FK, Bl + (size_t)32 * FK, FF, FK);

    for (int c = 0; c < NC; c++) {
        if (c < NC - 1) asm volatile("cp.async.wait_group 1;" ::: "memory");
        else            asm volatile("cp.async.wait_group 0;" ::: "memory");
        __syncthreads();
        if (c + 2 < NC) {
            const int cn = c + 2;
            load_chunk4(sb + (cn % 3) * STAGE_BYTES, tid,
                        Ah + cn * 32, Al + cn * 32,
                        Bh + (size_t)(cn * 32) * FK, Bl + (size_t)(cn * 32) * FK, FF, FK);
        }
        compute_chunk_g1(sb + (c % 3) * STAGE_BYTES, lane, wm, wn, acc);
        __syncthreads();
    }

    // epilogue: fp16 hi/lo feats in [h][b][n][k]
    const int b = rT >> 3;
    const size_t fbase = ((size_t)(h * BATCH + b) << 20);
    const int nrow0 = (rT & 7) * 128;
#pragma unroll
    for (int mi = 0; mi < 4; mi++)
#pragma unroll
        for (int ni = 0; ni < 4; ni++) {
            const int row0 = wm * 64 + mi * 16 + (lane >> 2);
            const int col0 = cT * 128 + wn * 32 + ni * 8 + (lane & 3) * 2;
#pragma unroll
            for (int half = 0; half < 2; half++) {
                const int n = nrow0 + row0 + half * 8;
                const float v0 = acc[mi][ni][half * 2];
                const float v1 = acc[mi][ni][half * 2 + 1];
                const uint32_t ph = pack_h2(v0, v1);
                const float2 hf = h2f2(ph);
                const uint32_t pl = pack_h2(v0 - hf.x, v1 - hf.y);
                const size_t off = fbase + (size_t)n * FK + col0;
                *reinterpret_cast<uint32_t*>(g_fhi + off) = ph;
                *reinterpret_cast<uint32_t*>(g_flo + off) = pl;
            }
        }
}

// ---------------------------------------------------------------------------
// GEMM2: out[b] = (1/3) sum_h attn[h,b] @ feats[h,b] + mean bias ; 2-pass
// ---------------------------------------------------------------------------
__global__ __launch_bounds__(256, 1) void gemm2_mma(const float* __restrict__ biases,
                                                    float* __restrict__ out) {
    extern __shared__ char smem[];
    const int tid = threadIdx.x, lane = tid & 31, wid = tid >> 5;
    const int wm = wid >> 2, wn = wid & 3;
    const uint32_t sb = smem_u32(smem);
    const int cT = blockIdx.x, nT = blockIdx.y, b = blockIdx.z;

    float acc[4][4][4];
#pragma unroll
    for (int i = 0; i < 4; i++)
#pragma unroll
        for (int j = 0; j < 4; j++)
#pragma unroll
            for (int k = 0; k < 4; k++) acc[i][j][k] = 0.f;

    const int NC = 96;
    auto issue = [&](int cn) {
        const int hh = cn >> 5, kc = cn & 31;
        const size_t hb = ((size_t)(hh * BATCH + b)) << 20;
        load_chunk3(sb + (cn % 3) * STAGE_BYTES, tid,
                    g_ath + hb + ((size_t)nT << 17) + kc * 32,
                    g_fhi + hb + ((size_t)(kc * 32) << 10) + cT * 128,
                    g_flo + hb + ((size_t)(kc * 32) << 10) + cT * 128, NN, FK);
    };
    issue(0);
    issue(1);

    for (int c = 0; c < NC; c++) {
        if (c < NC - 1) asm volatile("cp.async.wait_group 1;" ::: "memory");
        else            asm volatile("cp.async.wait_group 0;" ::: "memory");
        __syncthreads();
        if (c + 2 < NC) issue(c + 2);
        compute_chunk_g2(sb + (c % 3) * STAGE_BYTES, lane, wm, wn, acc);
        __syncthreads();
    }

    const float inv3 = 1.f / 3.f;
    const size_t obase = ((size_t)(H * BATCH + b) << 20) + ((size_t)nT << 17);
#pragma unroll
    for (int mi = 0; mi < 4; mi++)
#pragma unroll
        for (int ni = 0; ni < 4; ni++) {
            const int row0 = wm * 64 + mi * 16 + (lane >> 2);
            const int col0 = cT * 128 + wn * 32 + ni * 8 + (lane & 3) * 2;
            const float bm0 = (biases[col0] + biases[FK + col0] + biases[2 * FK + col0]) * inv3;
            const float bm1 = (biases[col0 + 1] + biases[FK + col0 + 1] + biases[2 * FK + col0 + 1]) * inv3;
#pragma unroll
            for (int half = 0; half < 2; half++) {
                const int n = row0 + half * 8;
                float2 v;
                v.x = acc[mi][ni][half * 2] * inv3 + bm0;
                v.y = acc[mi][ni][half * 2 + 1] * inv3 + bm1;
                *reinterpret_cast<float2*>(out + obase + (size_t)n * FK + col0) = v;
            }
        }
}

// ---------------------------------------------------------------------------
// prep: fp16 hi/lo splits (natural layouts)
// ---------------------------------------------------------------------------
__global__ __launch_bounds__(1024) void split_x(const float* __restrict__ x) {
    const size_t i = (size_t)blockIdx.x * 1024 + threadIdx.x;
    const float v = x[i];
    const __half hv = __float2half_rn(v);
    g_xhi[i] = hv;
    g_xlo[i] = __float2half_rn(v - __half2float(hv));
}
__global__ __launch_bounds__(1024) void split_w(const float* __restrict__ w) {
    const size_t i = (size_t)blockIdx.x * 1024 + threadIdx.x;
    const float v = w[i];
    const __half hv = __float2half_rn(v);
    g_whi[i] = hv;
    g_wlo[i] = __float2half_rn(v - __half2float(hv));
}

// ---------------------------------------------------------------------------
// s_self / s_neigh: one warp per (h,b,n) row; dual dot over k=1024 (hi+lo)
// ---------------------------------------------------------------------------
__global__ __launch_bounds__(256) void s_kernel(const float* __restrict__ a_self,
                                                const float* __restrict__ a_neigh) {
    const int r = blockIdx.x * 8 + (threadIdx.x >> 5);
    const int lane = threadIdx.x & 31;
    const int h = r >> 14;

    const uint4* fh = reinterpret_cast<const uint4*>(g_fhi + ((size_t)r << 10));
    const uint4* fl = reinterpret_cast<const uint4*>(g_flo + ((size_t)r << 10));
    const float4* as4 = reinterpret_cast<const float4*>(a_self + h * FK);
    const float4* an4 = reinterpret_cast<const float4*>(a_neigh + h * FK);

    float s0 = 0.f, s1 = 0.f;
#pragma unroll
    for (int i = lane; i < 128; i += 32) {
        const uint4 uh = fh[i];
        const uint4 ul = fl[i];
        const uint32_t* ph = reinterpret_cast<const uint32_t*>(&uh);
        const uint32_t* pl = reinterpret_cast<const uint32_t*>(&ul);
#pragma unroll
        for (int e = 0; e < 2; e++) {
            const float4 a = as4[i * 2 + e];
            const float4 nq = an4[i * 2 + e];
            const float2 h0 = h2f2(ph[e * 2]), l0 = h2f2(pl[e * 2]);
            const float2 h1 = h2f2(ph[e * 2 + 1]), l1 = h2f2(pl[e * 2 + 1]);
            const float f0 = h0.x + l0.x, f1 = h0.y + l0.y;
            const float f2 = h1.x + l1.x, f3 = h1.y + l1.y;
            s0 += f0 * a.x + f1 * a.y + f2 * a.z + f3 * a.w;
            s1 += f0 * nq.x + f1 * nq.y + f2 * nq.z + f3 * nq.w;
        }
    }
#pragma unroll
    for (int o = 16; o; o >>= 1) {
        s0 += __shfl_xor_sync(0xFFFFFFFFu, s0, o);
        s1 += __shfl_xor_sync(0xFFFFFFFFu, s1, o);
    }
    if (lane == 0) {
        g_sself[r] = s0;
        g_sneigh[r] = s1;
    }
}

// ---------------------------------------------------------------------------
// softmax: fp32 attn into out slab + single fp16 copy for GEMM2
// ---------------------------------------------------------------------------
__global__ __launch_bounds__(256) void softmax_kernel(float* __restrict__ out) {
    const int r = blockIdx.x;
    const int hb = r >> 10;
    const int tid = threadIdx.x;

    const float si = g_sself[r];
    const float* sn = g_sneigh + (size_t)hb * NN;

    __shared__ float redmax[8], redsum[8];
    __shared__ float bmax, bsum;

    float lv[4];
    float m = -1e30f;
#pragma unroll
    for (int jj = 0; jj < 4; jj++) {
        const int j = tid + jj * 256;
        float v = si + sn[j];
        v = (v >= 0.f) ? v : 0.2f * v;
        lv[jj] = v;
        m = fmaxf(m, v);
    }
#pragma unroll
    for (int o = 16; o; o >>= 1) m = fmaxf(m, __shfl_xor_sync(0xFFFFFFFFu, m, o));
    if ((tid & 31) == 0) redmax[tid >> 5] = m;
    __syncthreads();
    if (tid == 0) {
        float t = redmax[0];
#pragma unroll
        for (int i = 1; i < 8; i++) t = fmaxf(t, redmax[i]);
        bmax = t;
    }
    __syncthreads();
    m = bmax;

    float sum = 0.f;
#pragma unroll
    for (int jj = 0; jj < 4; jj++) {
        lv[jj] = __expf(lv[jj] - m);
        sum += lv[jj];
    }
#pragma unroll
    for (int o = 16; o; o >>= 1) sum += __shfl_xor_sync(0xFFFFFFFFu, sum, o);
    if ((tid & 31) == 0) redsum[tid >> 5] = sum;
    __syncthreads();
    if (tid == 0) {
        float t = 0.f;
#pragma unroll
        for (int i = 0; i < 8; i++) t += redsum[i];
        bsum = t;
    }
    __syncthreads();
    const float inv = 1.f / bsum;

    const size_t rowoff = ((size_t)hb << 20) + ((size_t)(r & 1023) << 10);
    float* orow = out + rowoff;
#pragma unroll
    for (int jj = 0; jj < 4; jj++) {
        const int j = tid + jj * 256;
        const float p = lv[jj] * inv;
        orow[j] = p;
        g_ath[rowoff + j] = __float2half_rn(p);
    }
}

// ---------------------------------------------------------------------------
extern "C" void kernel_launch(void* const* d_in, const int* in_sizes, int n_in,
                              void* d_out, int out_size) {
    const float* x       = (const float*)d_in[0];
    const float* kernels = (const float*)d_in[1];
    const float* biases  = (const float*)d_in[2];
    const float* a_self  = (const float*)d_in[3];
    const float* a_neigh = (const float*)d_in[4];
    float* out = (float*)d_out;

    static bool attr_set = false;
    if (!attr_set) {
        cudaFuncSetAttribute(gemm1_mma, cudaFuncAttributeMaxDynamicSharedMemorySize, SMEM_BYTES);
        cudaFuncSetAttribute(gemm2_mma, cudaFuncAttributeMaxDynamicSharedMemorySize, SMEM_BYTES);
        attr_set = true;
    }

    split_x<<<(M1 * FF) / 1024, 1024>>>(x);
    split_w<<<(H * FF * FK) / 1024, 1024>>>(kernels);

    gemm1_mma<<<dim3(FK / 128, M1 / 128, H), 256, SMEM_BYTES>>>();

    s_kernel<<<(H * BATCH * NN) / 8, 256>>>(a_self, a_neigh);

    softmax_kernel<<<H * BATCH * NN, 256>>>(out);

    gemm2_mma<<<dim3(FK / 128, NN / 128, BATCH), 256, SMEM_BYTES>>>(biases, out);
}

// round 9
// speedup vs baseline: 3.8692x; 1.2945x over previous
#include <cuda_runtime.h>
#include <cuda_fp16.h>
#include <cstdint>

#define H 3
#define BATCH 16
#define NN 1024
#define FF 512
#define FK 1024
#define M1 (BATCH * NN)

// ---------------------------------------------------------------------------
// scratch (static device allocations)
// ---------------------------------------------------------------------------
__device__ __align__(16) __half g_xhi[(size_t)M1 * FF];
__device__ __align__(16) __half g_xlo[(size_t)M1 * FF];
__device__ __align__(16) __half g_whi[(size_t)H * FF * FK];          // [h][f][k]
__device__ __align__(16) __half g_wlo[(size_t)H * FF * FK];
__device__ __align__(16) __half g_fhi[(size_t)H * BATCH * NN * FK];  // [h][b][n][k]
__device__ __align__(16) __half g_flo[(size_t)H * BATCH * NN * FK];
__device__ __align__(16) __half g_ath[(size_t)H * BATCH * NN * NN];  // [h][b][n][m] fp16
__device__ float g_sself[H * BATCH * NN];
__device__ float g_sneigh[H * BATCH * NN];

// ---------------------------------------------------------------------------
// PTX helpers (plain compute_103-legal: cp.async / ldmatrix / mma.sync fp16)
// ---------------------------------------------------------------------------
__device__ __forceinline__ uint32_t smem_u32(const void* p) {
    uint32_t a;
    asm("{ .reg .u64 t; cvta.to.shared.u64 t, %1; cvt.u32.u64 %0, t; }" : "=r"(a) : "l"(p));
    return a;
}
__device__ __forceinline__ void cpa16(uint32_t dst, const void* src) {
    asm volatile("cp.async.cg.shared.global [%0], [%1], 16;" :: "r"(dst), "l"(src));
}
#define CP_COMMIT() asm volatile("cp.async.commit_group;" ::: "memory")

__device__ __forceinline__ void ldsm4(uint32_t r[4], uint32_t addr) {
    asm volatile("ldmatrix.sync.aligned.m8n8.x4.shared.b16 {%0,%1,%2,%3}, [%4];"
                 : "=r"(r[0]), "=r"(r[1]), "=r"(r[2]), "=r"(r[3]) : "r"(addr));
}
__device__ __forceinline__ void ldsm4t(uint32_t r[4], uint32_t addr) {
    asm volatile("ldmatrix.sync.aligned.m8n8.x4.trans.shared.b16 {%0,%1,%2,%3}, [%4];"
                 : "=r"(r[0]), "=r"(r[1]), "=r"(r[2]), "=r"(r[3]) : "r"(addr));
}
__device__ __forceinline__ void mma16816(float c[4], const uint32_t a[4],
                                         uint32_t b0, uint32_t b1) {
    asm volatile(
        "mma.sync.aligned.m16n8k16.row.col.f32.f16.f16.f32 "
        "{%0,%1,%2,%3}, {%4,%5,%6,%7}, {%8,%9}, {%0,%1,%2,%3};"
        : "+f"(c[0]), "+f"(c[1]), "+f"(c[2]), "+f"(c[3])
        : "r"(a[0]), "r"(a[1]), "r"(a[2]), "r"(a[3]), "r"(b0), "r"(b1));
}

__device__ __forceinline__ uint32_t pack_h2(float a, float b) {
    __half2 t = __floats2half2_rn(a, b);
    return *reinterpret_cast<uint32_t*>(&t);
}
__device__ __forceinline__ float2 h2f2(uint32_t w) {
    __half2 t = *reinterpret_cast<__half2*>(&w);
    return __half22float2(t);
}

// ---------------------------------------------------------------------------
// GEMM1 smem: 3 stages; per stage: A hi/lo 128x32 (pad 80B), B hi/lo 32x128 (pad 272B)
// ---------------------------------------------------------------------------
#define A_STRIDE 80
#define B_STRIDE 272
#define OFF_AH 0
#define OFF_AL 10240
#define OFF_BH 20480
#define OFF_BL 29184
#define STAGE_BYTES 37888
#define SMEM1_BYTES (STAGE_BYTES * 3)   // 113664

// GEMM2 smem: 3 stages; per stage: A 128x32 (pad 80B) + B 32x128 (pad 272B)
#define G2_OFF_A 0
#define G2_OFF_B 10240
#define G2_STAGE 18944
#define SMEM2_BYTES (G2_STAGE * 3)      // 56832

// gemm1: A hi/lo + B hi/lo (4 arrays)
__device__ __forceinline__ void load_chunk4(uint32_t sst, int tid,
                                            const __half* __restrict__ ah,
                                            const __half* __restrict__ al,
                                            const __half* __restrict__ bh,
                                            const __half* __restrict__ bl,
                                            int lda, int ldb) {
#pragma unroll
    for (int i = 0; i < 2; i++) {
        const int u = tid + 256 * i;
        const int row = u >> 2, seg = u & 3;
        cpa16(sst + OFF_AH + row * A_STRIDE + seg * 16, ah + (size_t)row * lda + seg * 8);
        cpa16(sst + OFF_AL + row * A_STRIDE + seg * 16, al + (size_t)row * lda + seg * 8);
    }
#pragma unroll
    for (int i = 0; i < 2; i++) {
        const int u = tid + 256 * i;
        const int row = u >> 4, seg = u & 15;
        cpa16(sst + OFF_BH + row * B_STRIDE + seg * 16, bh + (size_t)row * ldb + seg * 8);
        cpa16(sst + OFF_BL + row * B_STRIDE + seg * 16, bl + (size_t)row * ldb + seg * 8);
    }
    CP_COMMIT();
}

// gemm2: A single + B single (2 arrays)
__device__ __forceinline__ void load_chunk2(uint32_t sst, int tid,
                                            const __half* __restrict__ a,
                                            const __half* __restrict__ b,
                                            int lda, int ldb) {
#pragma unroll
    for (int i = 0; i < 2; i++) {
        const int u = tid + 256 * i;
        const int row = u >> 2, seg = u & 3;
        cpa16(sst + G2_OFF_A + row * A_STRIDE + seg * 16, a + (size_t)row * lda + seg * 8);
    }
#pragma unroll
    for (int i = 0; i < 2; i++) {
        const int u = tid + 256 * i;
        const int row = u >> 4, seg = u & 15;
        cpa16(sst + G2_OFF_B + row * B_STRIDE + seg * 16, b + (size_t)row * ldb + seg * 8);
    }
    CP_COMMIT();
}

// gemm1 chunk: acc += Ah*Bh + Ah*Bl + Al*Bh
__device__ __forceinline__ void compute_chunk_g1(uint32_t sst, int lane, int wm, int wn,
                                                 float acc[4][4][4]) {
#pragma unroll
    for (int kk = 0; kk < 32; kk += 16) {
        uint32_t Ah[4][4], Al[4][4], Bh[2][4], Bl[2][4];
        const uint32_t arow = wm * 64 + (lane & 7) + ((lane >> 3) & 1) * 8;
        const uint32_t acoff = (kk + (lane >> 4) * 8) * 2;
#pragma unroll
        for (int mi = 0; mi < 4; mi++) {
            const uint32_t ad = sst + OFF_AH + (arow + mi * 16) * A_STRIDE + acoff;
            ldsm4(Ah[mi], ad);
            ldsm4(Al[mi], ad + (OFF_AL - OFF_AH));
        }
        const uint32_t brow = kk + ((lane >> 3) & 1) * 8 + (lane & 7);
        const uint32_t bcoff = (wn * 32 + (lane >> 4) * 8) * 2;
#pragma unroll
        for (int np = 0; np < 2; np++) {
            const uint32_t bd = sst + OFF_BH + brow * B_STRIDE + bcoff + np * 32;
            ldsm4t(Bh[np], bd);
            ldsm4t(Bl[np], bd + (OFF_BL - OFF_BH));
        }
#pragma unroll
        for (int mi = 0; mi < 4; mi++)
#pragma unroll
            for (int ni = 0; ni < 4; ni++)
                mma16816(acc[mi][ni], Ah[mi], Bh[ni >> 1][(ni & 1) * 2], Bh[ni >> 1][(ni & 1) * 2 + 1]);
#pragma unroll
        for (int mi = 0; mi < 4; mi++)
#pragma unroll
            for (int ni = 0; ni < 4; ni++)
                mma16816(acc[mi][ni], Ah[mi], Bl[ni >> 1][(ni & 1) * 2], Bl[ni >> 1][(ni & 1) * 2 + 1]);
#pragma unroll
        for (int mi = 0; mi < 4; mi++)
#pragma unroll
            for (int ni = 0; ni < 4; ni++)
                mma16816(acc[mi][ni], Al[mi], Bh[ni >> 1][(ni & 1) * 2], Bh[ni >> 1][(ni & 1) * 2 + 1]);
    }
}

// gemm2 chunk: acc += A*B   (single pass)
__device__ __forceinline__ void compute_chunk_g2(uint32_t sst, int lane, int wm, int wn,
                                                 float acc[4][4][4]) {
#pragma unroll
    for (int kk = 0; kk < 32; kk += 16) {
        uint32_t A[4][4], B[2][4];
        const uint32_t arow = wm * 64 + (lane & 7) + ((lane >> 3) & 1) * 8;
        const uint32_t acoff = (kk + (lane >> 4) * 8) * 2;
#pragma unroll
        for (int mi = 0; mi < 4; mi++)
            ldsm4(A[mi], sst + G2_OFF_A + (arow + mi * 16) * A_STRIDE + acoff);
        const uint32_t brow = kk + ((lane >> 3) & 1) * 8 + (lane & 7);
        const uint32_t bcoff = (wn * 32 + (lane >> 4) * 8) * 2;
#pragma unroll
        for (int np = 0; np < 2; np++)
            ldsm4t(B[np], sst + G2_OFF_B + brow * B_STRIDE + bcoff + np * 32);
#pragma unroll
        for (int mi = 0; mi < 4; mi++)
#pragma unroll
            for (int ni = 0; ni < 4; ni++)
                mma16816(acc[mi][ni], A[mi], B[ni >> 1][(ni & 1) * 2], B[ni >> 1][(ni & 1) * 2 + 1]);
    }
}

// ---------------------------------------------------------------------------
// GEMM1: feats[h] = X (16384x512) @ W[h] (512x1024); 3-pass; stores fp16 hi/lo
// ---------------------------------------------------------------------------
__global__ __launch_bounds__(256, 1) void gemm1_mma() {
    extern __shared__ char smem[];
    const int tid = threadIdx.x, lane = tid & 31, wid = tid >> 5;
    const int wm = wid >> 2, wn = wid & 3;
    const uint32_t sb = smem_u32(smem);
    const int cT = blockIdx.x, rT = blockIdx.y, h = blockIdx.z;

    const __half* Ah = g_xhi + (size_t)rT * 128 * FF;
    const __half* Al = g_xlo + (size_t)rT * 128 * FF;
    const __half* Bh = g_whi + (size_t)h * FF * FK + (size_t)cT * 128;
    const __half* Bl = g_wlo + (size_t)h * FF * FK + (size_t)cT * 128;

    float acc[4][4][4];
#pragma unroll
    for (int i = 0; i < 4; i++)
#pragma unroll
        for (int j = 0; j < 4; j++)
#pragma unroll
            for (int k = 0; k < 4; k++) acc[i][j][k] = 0.f;

    const int NC = FF / 32;  // 16
    load_chunk4(sb, tid, Ah, Al, Bh, Bl, FF, FK);
    load_chunk4(sb + STAGE_BYTES, tid, Ah + 32, Al + 32,
                Bh + (size_t)32 * FK, Bl + (size_t)32 * FK, FF, FK);

    for (int c = 0; c < NC; c++) {
        if (c < NC - 1) asm volatile("cp.async.wait_group 1;" ::: "memory");
        else            asm volatile("cp.async.wait_group 0;" ::: "memory");
        __syncthreads();
        if (c + 2 < NC) {
            const int cn = c + 2;
            load_chunk4(sb + (cn % 3) * STAGE_BYTES, tid,
                        Ah + cn * 32, Al + cn * 32,
                        Bh + (size_t)(cn * 32) * FK, Bl + (size_t)(cn * 32) * FK, FF, FK);
        }
        compute_chunk_g1(sb + (c % 3) * STAGE_BYTES, lane, wm, wn, acc);
        __syncthreads();
    }

    // epilogue: fp16 hi/lo feats in [h][b][n][k]
    const int b = rT >> 3;
    const size_t fbase = ((size_t)(h * BATCH + b) << 20);
    const int nrow0 = (rT & 7) * 128;
#pragma unroll
    for (int mi = 0; mi < 4; mi++)
#pragma unroll
        for (int ni = 0; ni < 4; ni++) {
            const int row0 = wm * 64 + mi * 16 + (lane >> 2);
            const int col0 = cT * 128 + wn * 32 + ni * 8 + (lane & 3) * 2;
#pragma unroll
            for (int half = 0; half < 2; half++) {
                const int n = nrow0 + row0 + half * 8;
                const float v0 = acc[mi][ni][half * 2];
                const float v1 = acc[mi][ni][half * 2 + 1];
                const uint32_t ph = pack_h2(v0, v1);
                const float2 hf = h2f2(ph);
                const uint32_t pl = pack_h2(v0 - hf.x, v1 - hf.y);
                const size_t off = fbase + (size_t)n * FK + col0;
                *reinterpret_cast<uint32_t*>(g_fhi + off) = ph;
                *reinterpret_cast<uint32_t*>(g_flo + off) = pl;
            }
        }
}

// ---------------------------------------------------------------------------
// GEMM2: out[b] = (1/3) sum_h attn[h,b] @ feats_hi[h,b] + mean bias ; 1-pass
// ---------------------------------------------------------------------------
__global__ __launch_bounds__(256) void gemm2_mma(const float* __restrict__ biases,
                                                 float* __restrict__ out) {
    extern __shared__ char smem[];
    const int tid = threadIdx.x, lane = tid & 31, wid = tid >> 5;
    const int wm = wid >> 2, wn = wid & 3;
    const uint32_t sb = smem_u32(smem);
    const int cT = blockIdx.x, nT = blockIdx.y, b = blockIdx.z;

    float acc[4][4][4];
#pragma unroll
    for (int i = 0; i < 4; i++)
#pragma unroll
        for (int j = 0; j < 4; j++)
#pragma unroll
            for (int k = 0; k < 4; k++) acc[i][j][k] = 0.f;

    const int NC = 96;
    auto issue = [&](int cn) {
        const int hh = cn >> 5, kc = cn & 31;
        const size_t hb = ((size_t)(hh * BATCH + b)) << 20;
        load_chunk2(sb + (cn % 3) * G2_STAGE, tid,
                    g_ath + hb + ((size_t)nT << 17) + kc * 32,
                    g_fhi + hb + ((size_t)(kc * 32) << 10) + cT * 128, NN, FK);
    };
    issue(0);
    issue(1);

    for (int c = 0; c < NC; c++) {
        if (c < NC - 1) asm volatile("cp.async.wait_group 1;" ::: "memory");
        else            asm volatile("cp.async.wait_group 0;" ::: "memory");
        __syncthreads();
        if (c + 2 < NC) issue(c + 2);
        compute_chunk_g2(sb + (c % 3) * G2_STAGE, lane, wm, wn, acc);
        __syncthreads();
    }

    const float inv3 = 1.f / 3.f;
    const size_t obase = ((size_t)(H * BATCH + b) << 20) + ((size_t)nT << 17);
#pragma unroll
    for (int mi = 0; mi < 4; mi++)
#pragma unroll
        for (int ni = 0; ni < 4; ni++) {
            const int row0 = wm * 64 + mi * 16 + (lane >> 2);
            const int col0 = cT * 128 + wn * 32 + ni * 8 + (lane & 3) * 2;
            const float bm0 = (biases[col0] + biases[FK + col0] + biases[2 * FK + col0]) * inv3;
            const float bm1 = (biases[col0 + 1] + biases[FK + col0 + 1] + biases[2 * FK + col0 + 1]) * inv3;
#pragma unroll
            for (int half = 0; half < 2; half++) {
                const int n = row0 + half * 8;
                float2 v;
                v.x = acc[mi][ni][half * 2] * inv3 + bm0;
                v.y = acc[mi][ni][half * 2 + 1] * inv3 + bm1;
                *reinterpret_cast<float2*>(out + obase + (size_t)n * FK + col0) = v;
            }
        }
}

// ---------------------------------------------------------------------------
// prep: fp16 hi/lo splits (natural layouts)
// ---------------------------------------------------------------------------
__global__ __launch_bounds__(1024) void split_x(const float* __restrict__ x) {
    const size_t i = (size_t)blockIdx.x * 1024 + threadIdx.x;
    const float v = x[i];
    const __half hv = __float2half_rn(v);
    g_xhi[i] = hv;
    g_xlo[i] = __float2half_rn(v - __half2float(hv));
}
__global__ __launch_bounds__(1024) void split_w(const float* __restrict__ w) {
    const size_t i = (size_t)blockIdx.x * 1024 + threadIdx.x;
    const float v = w[i];
    const __half hv = __float2half_rn(v);
    g_whi[i] = hv;
    g_wlo[i] = __float2half_rn(v - __half2float(hv));
}

// ---------------------------------------------------------------------------
// s_self / s_neigh: one warp per (h,b,n) row; dual dot over k=1024 (hi+lo)
// ---------------------------------------------------------------------------
__global__ __launch_bounds__(256) void s_kernel(const float* __restrict__ a_self,
                                                const float* __restrict__ a_neigh) {
    const int r = blockIdx.x * 8 + (threadIdx.x >> 5);
    const int lane = threadIdx.x & 31;
    const int h = r >> 14;

    const uint4* fh = reinterpret_cast<const uint4*>(g_fhi + ((size_t)r << 10));
    const uint4* fl = reinterpret_cast<const uint4*>(g_flo + ((size_t)r << 10));
    const float4* as4 = reinterpret_cast<const float4*>(a_self + h * FK);
    const float4* an4 = reinterpret_cast<const float4*>(a_neigh + h * FK);

    float s0 = 0.f, s1 = 0.f;
#pragma unroll
    for (int i = lane; i < 128; i += 32) {
        const uint4 uh = fh[i];
        const uint4 ul = fl[i];
        const uint32_t* ph = reinterpret_cast<const uint32_t*>(&uh);
        const uint32_t* pl = reinterpret_cast<const uint32_t*>(&ul);
#pragma unroll
        for (int e = 0; e < 2; e++) {
            const float4 a = as4[i * 2 + e];
            const float4 nq = an4[i * 2 + e];
            const float2 h0 = h2f2(ph[e * 2]), l0 = h2f2(pl[e * 2]);
            const float2 h1 = h2f2(ph[e * 2 + 1]), l1 = h2f2(pl[e * 2 + 1]);
            const float f0 = h0.x + l0.x, f1 = h0.y + l0.y;
            const float f2 = h1.x + l1.x, f3 = h1.y + l1.y;
            s0 += f0 * a.x + f1 * a.y + f2 * a.z + f3 * a.w;
            s1 += f0 * nq.x + f1 * nq.y + f2 * nq.z + f3 * nq.w;
        }
    }
#pragma unroll
    for (int o = 16; o; o >>= 1) {
        s0 += __shfl_xor_sync(0xFFFFFFFFu, s0, o);
        s1 += __shfl_xor_sync(0xFFFFFFFFu, s1, o);
    }
    if (lane == 0) {
        g_sself[r] = s0;
        g_sneigh[r] = s1;
    }
}

// ---------------------------------------------------------------------------
// softmax: fp32 attn into out slab + single fp16 copy for GEMM2
// ---------------------------------------------------------------------------
__global__ __launch_bounds__(256) void softmax_kernel(float* __restrict__ out) {
    const int r = blockIdx.x;
    const int hb = r >> 10;
    const int tid = threadIdx.x;

    const float si = g_sself[r];
    const float* sn = g_sneigh + (size_t)hb * NN;

    __shared__ float redmax[8], redsum[8];
    __shared__ float bmax, bsum;

    float lv[4];
    float m = -1e30f;
#pragma unroll
    for (int jj = 0; jj < 4; jj++) {
        const int j = tid + jj * 256;
        float v = si + sn[j];
        v = (v >= 0.f) ? v : 0.2f * v;
        lv[jj] = v;
        m = fmaxf(m, v);
    }
#pragma unroll
    for (int o = 16; o; o >>= 1) m = fmaxf(m, __shfl_xor_sync(0xFFFFFFFFu, m, o));
    if ((tid & 31) == 0) redmax[tid >> 5] = m;
    __syncthreads();
    if (tid == 0) {
        float t = redmax[0];
#pragma unroll
        for (int i = 1; i < 8; i++) t = fmaxf(t, redmax[i]);
        bmax = t;
    }
    __syncthreads();
    m = bmax;

    float sum = 0.f;
#pragma unroll
    for (int jj = 0; jj < 4; jj++) {
        lv[jj] = __expf(lv[jj] - m);
        sum += lv[jj];
    }
#pragma unroll
    for (int o = 16; o; o >>= 1) sum += __shfl_xor_sync(0xFFFFFFFFu, sum, o);
    if ((tid & 31) == 0) redsum[tid >> 5] = sum;
    __syncthreads();
    if (tid == 0) {
        float t = 0.f;
#pragma unroll
        for (int i = 0; i < 8; i++) t += redsum[i];
        bsum = t;
    }
    __syncthreads();
    const float inv = 1.f / bsum;

    const size_t rowoff = ((size_t)hb << 20) + ((size_t)(r & 1023) << 10);
    float* orow = out + rowoff;
#pragma unroll
    for (int jj = 0; jj < 4; jj++) {
        const int j = tid + jj * 256;
        const float p = lv[jj] * inv;
        orow[j] = p;
        g_ath[rowoff + j] = __float2half_rn(p);
    }
}

// ---------------------------------------------------------------------------
extern "C" void kernel_launch(void* const* d_in, const int* in_sizes, int n_in,
                              void* d_out, int out_size) {
    const float* x       = (const float*)d_in[0];
    const float* kernels = (const float*)d_in[1];
    const float* biases  = (const float*)d_in[2];
    const float* a_self  = (const float*)d_in[3];
    const float* a_neigh = (const float*)d_in[4];
    float* out = (float*)d_out;

    static bool attr_set = false;
    if (!attr_set) {
        cudaFuncSetAttribute(gemm1_mma, cudaFuncAttributeMaxDynamicSharedMemorySize, SMEM1_BYTES);
        cudaFuncSetAttribute(gemm2_mma, cudaFuncAttributeMaxDynamicSharedMemorySize, SMEM2_BYTES);
        attr_set = true;
    }

    split_x<<<(M1 * FF) / 1024, 1024>>>(x);
    split_w<<<(H * FF * FK) / 1024, 1024>>>(kernels);

    gemm1_mma<<<dim3(FK / 128, M1 / 128, H), 256, SMEM1_BYTES>>>();

    s_kernel<<<(H * BATCH * NN) / 8, 256>>>(a_self, a_neigh);

    softmax_kernel<<<H * BATCH * NN, 256>>>(out);

    gemm2_mma<<<dim3(FK / 128, NN / 128, BATCH), 256, SMEM2_BYTES>>>(biases, out);
}

// round 10
// speedup vs baseline: 5.2178x; 1.3485x over previous
#include <cuda_runtime.h>
#include <cuda_fp16.h>
#include <cstdint>

#define H 3
#define BATCH 16
#define NN 1024
#define FF 512
#define FK 1024
#define M1 (BATCH * NN)

// ---------------------------------------------------------------------------
// scratch (static device allocations)
// ---------------------------------------------------------------------------
__device__ __align__(16) __half g_xhi[(size_t)M1 * FF];
__device__ __align__(16) __half g_whi[(size_t)H * FF * FK];          // [h][f][k]
__device__ __align__(16) __half g_wlo[(size_t)H * FF * FK];
__device__ __align__(16) __half g_fhi[(size_t)H * BATCH * NN * FK];  // [h][b][n][k]
__device__ __align__(16) __half g_flo[(size_t)H * BATCH * NN * FK];
__device__ __align__(16) __half g_ath[(size_t)H * BATCH * NN * NN];  // [h][b][n][m] fp16
__device__ float g_sself[H * BATCH * NN];
__device__ float g_sneigh[H * BATCH * NN];

// ---------------------------------------------------------------------------
// PTX helpers (plain compute_103-legal: cp.async / ldmatrix / mma.sync fp16)
// ---------------------------------------------------------------------------
__device__ __forceinline__ uint32_t smem_u32(const void* p) {
    uint32_t a;
    asm("{ .reg .u64 t; cvta.to.shared.u64 t, %1; cvt.u32.u64 %0, t; }" : "=r"(a) : "l"(p));
    return a;
}
__device__ __forceinline__ void cpa16(uint32_t dst, const void* src) {
    asm volatile("cp.async.cg.shared.global [%0], [%1], 16;" :: "r"(dst), "l"(src));
}
#define CP_COMMIT() asm volatile("cp.async.commit_group;" ::: "memory")

__device__ __forceinline__ void ldsm4(uint32_t r[4], uint32_t addr) {
    asm volatile("ldmatrix.sync.aligned.m8n8.x4.shared.b16 {%0,%1,%2,%3}, [%4];"
                 : "=r"(r[0]), "=r"(r[1]), "=r"(r[2]), "=r"(r[3]) : "r"(addr));
}
__device__ __forceinline__ void ldsm4t(uint32_t r[4], uint32_t addr) {
    asm volatile("ldmatrix.sync.aligned.m8n8.x4.trans.shared.b16 {%0,%1,%2,%3}, [%4];"
                 : "=r"(r[0]), "=r"(r[1]), "=r"(r[2]), "=r"(r[3]) : "r"(addr));
}
__device__ __forceinline__ void mma16816(float c[4], const uint32_t a[4],
                                         uint32_t b0, uint32_t b1) {
    asm volatile(
        "mma.sync.aligned.m16n8k16.row.col.f32.f16.f16.f32 "
        "{%0,%1,%2,%3}, {%4,%5,%6,%7}, {%8,%9}, {%0,%1,%2,%3};"
        : "+f"(c[0]), "+f"(c[1]), "+f"(c[2]), "+f"(c[3])
        : "r"(a[0]), "r"(a[1]), "r"(a[2]), "r"(a[3]), "r"(b0), "r"(b1));
}

__device__ __forceinline__ uint32_t pack_h2(float a, float b) {
    __half2 t = __floats2half2_rn(a, b);
    return *reinterpret_cast<uint32_t*>(&t);
}
__device__ __forceinline__ float2 h2f2(uint32_t w) {
    __half2 t = *reinterpret_cast<__half2*>(&w);
    return __half22float2(t);
}

// ---------------------------------------------------------------------------
// smem layouts
// GEMM1 stage: A 128x32 (pad 80B) + Bh 32x128 (pad 272B) + Bl 32x128 (pad 272B)
// GEMM2 stage: A 128x32 (pad 80B) + B 32x128 (pad 272B)
// ---------------------------------------------------------------------------
#define A_STRIDE 80
#define B_STRIDE 272
#define G1_OFF_A  0
#define G1_OFF_BH 10240
#define G1_OFF_BL 18944
#define G1_STAGE  27648
#define SMEM1_BYTES (G1_STAGE * 3)      // 82944

#define G2_OFF_A 0
#define G2_OFF_B 10240
#define G2_STAGE 18944
#define SMEM2_BYTES (G2_STAGE * 3)      // 56832

// gemm1: A + B hi/lo (3 arrays)
__device__ __forceinline__ void load_chunk_g1(uint32_t sst, int tid,
                                              const __half* __restrict__ a,
                                              const __half* __restrict__ bh,
                                              const __half* __restrict__ bl,
                                              int lda, int ldb) {
#pragma unroll
    for (int i = 0; i < 2; i++) {
        const int u = tid + 256 * i;
        const int row = u >> 2, seg = u & 3;
        cpa16(sst + G1_OFF_A + row * A_STRIDE + seg * 16, a + (size_t)row * lda + seg * 8);
    }
#pragma unroll
    for (int i = 0; i < 2; i++) {
        const int u = tid + 256 * i;
        const int row = u >> 4, seg = u & 15;
        cpa16(sst + G1_OFF_BH + row * B_STRIDE + seg * 16, bh + (size_t)row * ldb + seg * 8);
        cpa16(sst + G1_OFF_BL + row * B_STRIDE + seg * 16, bl + (size_t)row * ldb + seg * 8);
    }
    CP_COMMIT();
}

// gemm2: A + B (2 arrays)
__device__ __forceinline__ void load_chunk_g2(uint32_t sst, int tid,
                                              const __half* __restrict__ a,
                                              const __half* __restrict__ b,
                                              int lda, int ldb) {
#pragma unroll
    for (int i = 0; i < 2; i++) {
        const int u = tid + 256 * i;
        const int row = u >> 2, seg = u & 3;
        cpa16(sst + G2_OFF_A + row * A_STRIDE + seg * 16, a + (size_t)row * lda + seg * 8);
    }
#pragma unroll
    for (int i = 0; i < 2; i++) {
        const int u = tid + 256 * i;
        const int row = u >> 4, seg = u & 15;
        cpa16(sst + G2_OFF_B + row * B_STRIDE + seg * 16, b + (size_t)row * ldb + seg * 8);
    }
    CP_COMMIT();
}

// gemm1 chunk: acc += A*Bh + A*Bl   (2-pass)
__device__ __forceinline__ void compute_chunk_g1(uint32_t sst, int lane, int wm, int wn,
                                                 float acc[4][4][4]) {
#pragma unroll
    for (int kk = 0; kk < 32; kk += 16) {
        uint32_t A[4][4], Bh[2][4], Bl[2][4];
        const uint32_t arow = wm * 64 + (lane & 7) + ((lane >> 3) & 1) * 8;
        const uint32_t acoff = (kk + (lane >> 4) * 8) * 2;
#pragma unroll
        for (int mi = 0; mi < 4; mi++)
            ldsm4(A[mi], sst + G1_OFF_A + (arow + mi * 16) * A_STRIDE + acoff);
        const uint32_t brow = kk + ((lane >> 3) & 1) * 8 + (lane & 7);
        const uint32_t bcoff = (wn * 32 + (lane >> 4) * 8) * 2;
#pragma unroll
        for (int np = 0; np < 2; np++) {
            const uint32_t bd = sst + G1_OFF_BH + brow * B_STRIDE + bcoff + np * 32;
            ldsm4t(Bh[np], bd);
            ldsm4t(Bl[np], bd + (G1_OFF_BL - G1_OFF_BH));
        }
#pragma unroll
        for (int mi = 0; mi < 4; mi++)
#pragma unroll
            for (int ni = 0; ni < 4; ni++)
                mma16816(acc[mi][ni], A[mi], Bh[ni >> 1][(ni & 1) * 2], Bh[ni >> 1][(ni & 1) * 2 + 1]);
#pragma unroll
        for (int mi = 0; mi < 4; mi++)
#pragma unroll
            for (int ni = 0; ni < 4; ni++)
                mma16816(acc[mi][ni], A[mi], Bl[ni >> 1][(ni & 1) * 2], Bl[ni >> 1][(ni & 1) * 2 + 1]);
    }
}

// gemm2 chunk: acc += A*B   (single pass)
__device__ __forceinline__ void compute_chunk_g2(uint32_t sst, int lane, int wm, int wn,
                                                 float acc[4][4][4]) {
#pragma unroll
    for (int kk = 0; kk < 32; kk += 16) {
        uint32_t A[4][4], B[2][4];
        const uint32_t arow = wm * 64 + (lane & 7) + ((lane >> 3) & 1) * 8;
        const uint32_t acoff = (kk + (lane >> 4) * 8) * 2;
#pragma unroll
        for (int mi = 0; mi < 4; mi++)
            ldsm4(A[mi], sst + G2_OFF_A + (arow + mi * 16) * A_STRIDE + acoff);
        const uint32_t brow = kk + ((lane >> 3) & 1) * 8 + (lane & 7);
        const uint32_t bcoff = (wn * 32 + (lane >> 4) * 8) * 2;
#pragma unroll
        for (int np = 0; np < 2; np++)
            ldsm4t(B[np], sst + G2_OFF_B + brow * B_STRIDE + bcoff + np * 32);
#pragma unroll
        for (int mi = 0; mi < 4; mi++)
#pragma unroll
            for (int ni = 0; ni < 4; ni++)
                mma16816(acc[mi][ni], A[mi], B[ni >> 1][(ni & 1) * 2], B[ni >> 1][(ni & 1) * 2 + 1]);
    }
}

// ---------------------------------------------------------------------------
// GEMM1: feats[h] = X (16384x512) @ W[h] (512x1024); 2-pass; stores fp16 hi/lo
// ---------------------------------------------------------------------------
__global__ __launch_bounds__(256, 2) void gemm1_mma() {
    extern __shared__ char smem[];
    const int tid = threadIdx.x, lane = tid & 31, wid = tid >> 5;
    const int wm = wid >> 2, wn = wid & 3;
    const uint32_t sb = smem_u32(smem);
    const int cT = blockIdx.x, rT = blockIdx.y, h = blockIdx.z;

    const __half* A  = g_xhi + (size_t)rT * 128 * FF;
    const __half* Bh = g_whi + (size_t)h * FF * FK + (size_t)cT * 128;
    const __half* Bl = g_wlo + (size_t)h * FF * FK + (size_t)cT * 128;

    float acc[4][4][4];
#pragma unroll
    for (int i = 0; i < 4; i++)
#pragma unroll
        for (int j = 0; j < 4; j++)
#pragma unroll
            for (int k = 0; k < 4; k++) acc[i][j][k] = 0.f;

    const int NC = FF / 32;  // 16
    load_chunk_g1(sb, tid, A, Bh, Bl, FF, FK);
    load_chunk_g1(sb + G1_STAGE, tid, A + 32,
                  Bh + (size_t)32 * FK, Bl + (size_t)32 * FK, FF, FK);

    for (int c = 0; c < NC; c++) {
        if (c < NC - 1) asm volatile("cp.async.wait_group 1;" ::: "memory");
        else            asm volatile("cp.async.wait_group 0;" ::: "memory");
        __syncthreads();
        if (c + 2 < NC) {
            const int cn = c + 2;
            load_chunk_g1(sb + (cn % 3) * G1_STAGE, tid, A + cn * 32,
                          Bh + (size_t)(cn * 32) * FK, Bl + (size_t)(cn * 32) * FK, FF, FK);
        }
        compute_chunk_g1(sb + (c % 3) * G1_STAGE, lane, wm, wn, acc);
        __syncthreads();
    }

    // epilogue: fp16 hi/lo feats in [h][b][n][k]
    const int b = rT >> 3;
    const size_t fbase = ((size_t)(h * BATCH + b) << 20);
    const int nrow0 = (rT & 7) * 128;
#pragma unroll
    for (int mi = 0; mi < 4; mi++)
#pragma unroll
        for (int ni = 0; ni < 4; ni++) {
            const int row0 = wm * 64 + mi * 16 + (lane >> 2);
            const int col0 = cT * 128 + wn * 32 + ni * 8 + (lane & 3) * 2;
#pragma unroll
            for (int half = 0; half < 2; half++) {
                const int n = nrow0 + row0 + half * 8;
                const float v0 = acc[mi][ni][half * 2];
                const float v1 = acc[mi][ni][half * 2 + 1];
                const uint32_t ph = pack_h2(v0, v1);
                const float2 hf = h2f2(ph);
                const uint32_t pl = pack_h2(v0 - hf.x, v1 - hf.y);
                const size_t off = fbase + (size_t)n * FK + col0;
                *reinterpret_cast<uint32_t*>(g_fhi + off) = ph;
                *reinterpret_cast<uint32_t*>(g_flo + off) = pl;
            }
        }
}

// ---------------------------------------------------------------------------
// GEMM2: out[b] = (1/3) sum_h attn[h,b] @ feats_hi[h,b] + mean bias ; 1-pass
// ---------------------------------------------------------------------------
__global__ __launch_bounds__(256, 2) void gemm2_mma(const float* __restrict__ biases,
                                                    float* __restrict__ out) {
    extern __shared__ char smem[];
    const int tid = threadIdx.x, lane = tid & 31, wid = tid >> 5;
    const int wm = wid >> 2, wn = wid & 3;
    const uint32_t sb = smem_u32(smem);
    const int cT = blockIdx.x, nT = blockIdx.y, b = blockIdx.z;

    float acc[4][4][4];
#pragma unroll
    for (int i = 0; i < 4; i++)
#pragma unroll
        for (int j = 0; j < 4; j++)
#pragma unroll
            for (int k = 0; k < 4; k++) acc[i][j][k] = 0.f;

    const int NC = 96;
    auto issue = [&](int cn) {
        const int hh = cn >> 5, kc = cn & 31;
        const size_t hb = ((size_t)(hh * BATCH + b)) << 20;
        load_chunk_g2(sb + (cn % 3) * G2_STAGE, tid,
                      g_ath + hb + ((size_t)nT << 17) + kc * 32,
                      g_fhi + hb + ((size_t)(kc * 32) << 10) + cT * 128, NN, FK);
    };
    issue(0);
    issue(1);

    for (int c = 0; c < NC; c++) {
        if (c < NC - 1) asm volatile("cp.async.wait_group 1;" ::: "memory");
        else            asm volatile("cp.async.wait_group 0;" ::: "memory");
        __syncthreads();
        if (c + 2 < NC) issue(c + 2);
        compute_chunk_g2(sb + (c % 3) * G2_STAGE, lane, wm, wn, acc);
        __syncthreads();
    }

    const float inv3 = 1.f / 3.f;
    const size_t obase = ((size_t)(H * BATCH + b) << 20) + ((size_t)nT << 17);
#pragma unroll
    for (int mi = 0; mi < 4; mi++)
#pragma unroll
        for (int ni = 0; ni < 4; ni++) {
            const int row0 = wm * 64 + mi * 16 + (lane >> 2);
            const int col0 = cT * 128 + wn * 32 + ni * 8 + (lane & 3) * 2;
            const float bm0 = (biases[col0] + biases[FK + col0] + biases[2 * FK + col0]) * inv3;
            const float bm1 = (biases[col0 + 1] + biases[FK + col0 + 1] + biases[2 * FK + col0 + 1]) * inv3;
#pragma unroll
            for (int half = 0; half < 2; half++) {
                const int n = row0 + half * 8;
                float2 v;
                v.x = acc[mi][ni][half * 2] * inv3 + bm0;
                v.y = acc[mi][ni][half * 2 + 1] * inv3 + bm1;
                *reinterpret_cast<float2*>(out + obase + (size_t)n * FK + col0) = v;
            }
        }
}

// ---------------------------------------------------------------------------
// prep: x -> fp16 (hi only); w -> fp16 hi/lo
// ---------------------------------------------------------------------------
__global__ __launch_bounds__(1024) void split_x(const float* __restrict__ x) {
    const size_t i = (size_t)blockIdx.x * 1024 + threadIdx.x;
    g_xhi[i] = __float2half_rn(x[i]);
}
__global__ __launch_bounds__(1024) void split_w(const float* __restrict__ w) {
    const size_t i = (size_t)blockIdx.x * 1024 + threadIdx.x;
    const float v = w[i];
    const __half hv = __float2half_rn(v);
    g_whi[i] = hv;
    g_wlo[i] = __float2half_rn(v - __half2float(hv));
}

// ---------------------------------------------------------------------------
// s_self / s_neigh: one warp per (h,b,n) row; dual dot over k=1024 (hi+lo)
// ---------------------------------------------------------------------------
__global__ __launch_bounds__(256) void s_kernel(const float* __restrict__ a_self,
                                                const float* __restrict__ a_neigh) {
    const int r = blockIdx.x * 8 + (threadIdx.x >> 5);
    const int lane = threadIdx.x & 31;
    const int h = r >> 14;

    const uint4* fh = reinterpret_cast<const uint4*>(g_fhi + ((size_t)r << 10));
    const uint4* fl = reinterpret_cast<const uint4*>(g_flo + ((size_t)r << 10));
    const float4* as4 = reinterpret_cast<const float4*>(a_self + h * FK);
    const float4* an4 = reinterpret_cast<const float4*>(a_neigh + h * FK);

    float s0 = 0.f, s1 = 0.f;
#pragma unroll
    for (int i = lane; i < 128; i += 32) {
        const uint4 uh = fh[i];
        const uint4 ul = fl[i];
        const uint32_t* ph = reinterpret_cast<const uint32_t*>(&uh);
        const uint32_t* pl = reinterpret_cast<const uint32_t*>(&ul);
#pragma unroll
        for (int e = 0; e < 2; e++) {
            const float4 a = as4[i * 2 + e];
            const float4 nq = an4[i * 2 + e];
            const float2 h0 = h2f2(ph[e * 2]), l0 = h2f2(pl[e * 2]);
            const float2 h1 = h2f2(ph[e * 2 + 1]), l1 = h2f2(pl[e * 2 + 1]);
            const float f0 = h0.x + l0.x, f1 = h0.y + l0.y;
            const float f2 = h1.x + l1.x, f3 = h1.y + l1.y;
            s0 += f0 * a.x + f1 * a.y + f2 * a.z + f3 * a.w;
            s1 += f0 * nq.x + f1 * nq.y + f2 * nq.z + f3 * nq.w;
        }
    }
#pragma unroll
    for (int o = 16; o; o >>= 1) {
        s0 += __shfl_xor_sync(0xFFFFFFFFu, s0, o);
        s1 += __shfl_xor_sync(0xFFFFFFFFu, s1, o);
    }
    if (lane == 0) {
        g_sself[r] = s0;
        g_sneigh[r] = s1;
    }
}

// ---------------------------------------------------------------------------
// softmax: fp32 attn into out slab + single fp16 copy for GEMM2
// ---------------------------------------------------------------------------
__global__ __launch_bounds__(256) void softmax_kernel(float* __restrict__ out) {
    const int r = blockIdx.x;
    const int hb = r >> 10;
    const int tid = threadIdx.x;

    const float si = g_sself[r];
    const float* sn = g_sneigh + (size_t)hb * NN;

    __shared__ float redmax[8], redsum[8];
    __shared__ float bmax, bsum;

    float lv[4];
    float m = -1e30f;
#pragma unroll
    for (int jj = 0; jj < 4; jj++) {
        const int j = tid + jj * 256;
        float v = si + sn[j];
        v = (v >= 0.f) ? v : 0.2f * v;
        lv[jj] = v;
        m = fmaxf(m, v);
    }
#pragma unroll
    for (int o = 16; o; o >>= 1) m = fmaxf(m, __shfl_xor_sync(0xFFFFFFFFu, m, o));
    if ((tid & 31) == 0) redmax[tid >> 5] = m;
    __syncthreads();
    if (tid == 0) {
        float t = redmax[0];
#pragma unroll
        for (int i = 1; i < 8; i++) t = fmaxf(t, redmax[i]);
        bmax = t;
    }
    __syncthreads();
    m = bmax;

    float sum = 0.f;
#pragma unroll
    for (int jj = 0; jj < 4; jj++) {
        lv[jj] = __expf(lv[jj] - m);
        sum += lv[jj];
    }
#pragma unroll
    for (int o = 16; o; o >>= 1) sum += __shfl_xor_sync(0xFFFFFFFFu, sum, o);
    if ((tid & 31) == 0) redsum[tid >> 5] = sum;
    __syncthreads();
    if (tid == 0) {
        float t = 0.f;
#pragma unroll
        for (int i = 0; i < 8; i++) t += redsum[i];
        bsum = t;
    }
    __syncthreads();
    const float inv = 1.f / bsum;

    const size_t rowoff = ((size_t)hb << 20) + ((size_t)(r & 1023) << 10);
    float* orow = out + rowoff;
#pragma unroll
    for (int jj = 0; jj < 4; jj++) {
        const int j = tid + jj * 256;
        const float p = lv[jj] * inv;
        orow[j] = p;
        g_ath[rowoff + j] = __float2half_rn(p);
    }
}

// ---------------------------------------------------------------------------
extern "C" void kernel_launch(void* const* d_in, const int* in_sizes, int n_in,
                              void* d_out, int out_size) {
    const float* x       = (const float*)d_in[0];
    const float* kernels = (const float*)d_in[1];
    const float* biases  = (const float*)d_in[2];
    const float* a_self  = (const float*)d_in[3];
    const float* a_neigh = (const float*)d_in[4];
    float* out = (float*)d_out;

    static bool attr_set = false;
    if (!attr_set) {
        cudaFuncSetAttribute(gemm1_mma, cudaFuncAttributeMaxDynamicSharedMemorySize, SMEM1_BYTES);
        cudaFuncSetAttribute(gemm2_mma, cudaFuncAttributeMaxDynamicSharedMemorySize, SMEM2_BYTES);
        attr_set = true;
    }

    split_x<<<(M1 * FF) / 1024, 1024>>>(x);
    split_w<<<(H * FF * FK) / 1024, 1024>>>(kernels);

    gemm1_mma<<<dim3(FK / 128, M1 / 128, H), 256, SMEM1_BYTES>>>();

    s_kernel<<<(H * BATCH * NN) / 8, 256>>>(a_self, a_neigh);

    softmax_kernel<<<H * BATCH * NN, 256>>>(out);

    gemm2_mma<<<dim3(FK / 128, NN / 128, BATCH), 256, SMEM2_BYTES>>>(biases, out);
}

// round 13
// speedup vs baseline: 5.6751x; 1.0877x over previous
#include <cuda_runtime.h>
#include <cuda_fp16.h>
#include <cstdint>

#define H 3
#define BATCH 16
#define NN 1024
#define FF 512
#define FK 1024
#define M1 (BATCH * NN)

// ---------------------------------------------------------------------------
// scratch (static device allocations)
// ---------------------------------------------------------------------------
__device__ __align__(16) __half g_xhi[(size_t)M1 * FF];
__device__ __align__(16) __half g_whi[(size_t)H * FF * FK];          // [h][f][k]
__device__ __align__(16) __half g_wlo[(size_t)H * FF * FK];
__device__ __align__(16) __half g_fhi[(size_t)H * BATCH * NN * FK];  // [h][b][n][k]
__device__ __align__(16) __half g_ath[(size_t)H * BATCH * NN * NN];  // [h][b][n][m] fp16
__device__ float g_sself[H * BATCH * NN];
__device__ float g_sneigh[H * BATCH * NN];

// ---------------------------------------------------------------------------
// PTX helpers (plain compute_103-legal: cp.async / ldmatrix / mma.sync fp16)
// ---------------------------------------------------------------------------
__device__ __forceinline__ uint32_t smem_u32(const void* p) {
    uint32_t a;
    asm("{ .reg .u64 t; cvta.to.shared.u64 t, %1; cvt.u32.u64 %0, t; }" : "=r"(a) : "l"(p));
    return a;
}
__device__ __forceinline__ void cpa16(uint32_t dst, const void* src) {
    asm volatile("cp.async.cg.shared.global [%0], [%1], 16;" :: "r"(dst), "l"(src));
}
#define CP_COMMIT() asm volatile("cp.async.commit_group;" ::: "memory")

__device__ __forceinline__ void ldsm4(uint32_t r[4], uint32_t addr) {
    asm volatile("ldmatrix.sync.aligned.m8n8.x4.shared.b16 {%0,%1,%2,%3}, [%4];"
                 : "=r"(r[0]), "=r"(r[1]), "=r"(r[2]), "=r"(r[3]) : "r"(addr));
}
__device__ __forceinline__ void ldsm4t(uint32_t r[4], uint32_t addr) {
    asm volatile("ldmatrix.sync.aligned.m8n8.x4.trans.shared.b16 {%0,%1,%2,%3}, [%4];"
                 : "=r"(r[0]), "=r"(r[1]), "=r"(r[2]), "=r"(r[3]) : "r"(addr));
}
__device__ __forceinline__ void mma16816(float c[4], const uint32_t a[4],
                                         uint32_t b0, uint32_t b1) {
    asm volatile(
        "mma.sync.aligned.m16n8k16.row.col.f32.f16.f16.f32 "
        "{%0,%1,%2,%3}, {%4,%5,%6,%7}, {%8,%9}, {%0,%1,%2,%3};"
        : "+f"(c[0]), "+f"(c[1]), "+f"(c[2]), "+f"(c[3])
        : "r"(a[0]), "r"(a[1]), "r"(a[2]), "r"(a[3]), "r"(b0), "r"(b1));
}

__device__ __forceinline__ uint32_t pack_h2(float a, float b) {
    __half2 t = __floats2half2_rn(a, b);
    return *reinterpret_cast<uint32_t*>(&t);
}
__device__ __forceinline__ float2 h2f2(uint32_t w) {
    __half2 t = *reinterpret_cast<__half2*>(&w);
    return __half22float2(t);
}

// ---------------------------------------------------------------------------
// smem layouts
// GEMM1 stage: A 128x32 (pad 80B) + Bh 32x128 (pad 272B) + Bl 32x128 (pad 272B)
// GEMM2 stage: A 128x32 (pad 80B) + B 32x128 (pad 272B)
// ---------------------------------------------------------------------------
#define A_STRIDE 80
#define B_STRIDE 272
#define G1_OFF_A  0
#define G1_OFF_BH 10240
#define G1_OFF_BL 18944
#define G1_STAGE  27648
#define SMEM1_BYTES (G1_STAGE * 3)      // 82944

#define G2_OFF_A 0
#define G2_OFF_B 10240
#define G2_STAGE 18944
#define SMEM2_BYTES (G2_STAGE * 3)      // 56832

// gemm1: A + B hi/lo (3 arrays)
__device__ __forceinline__ void load_chunk_g1(uint32_t sst, int tid,
                                              const __half* __restrict__ a,
                                              const __half* __restrict__ bh,
                                              const __half* __restrict__ bl,
                                              int lda, int ldb) {
#pragma unroll
    for (int i = 0; i < 2; i++) {
        const int u = tid + 256 * i;
        const int row = u >> 2, seg = u & 3;
        cpa16(sst + G1_OFF_A + row * A_STRIDE + seg * 16, a + (size_t)row * lda + seg * 8);
    }
#pragma unroll
    for (int i = 0; i < 2; i++) {
        const int u = tid + 256 * i;
        const int row = u >> 4, seg = u & 15;
        cpa16(sst + G1_OFF_BH + row * B_STRIDE + seg * 16, bh + (size_t)row * ldb + seg * 8);
        cpa16(sst + G1_OFF_BL + row * B_STRIDE + seg * 16, bl + (size_t)row * ldb + seg * 8);
    }
    CP_COMMIT();
}

// gemm2: A + B (2 arrays)
__device__ __forceinline__ void load_chunk_g2(uint32_t sst, int tid,
                                              const __half* __restrict__ a,
                                              const __half* __restrict__ b,
                                              int lda, int ldb) {
#pragma unroll
    for (int i = 0; i < 2; i++) {
        const int u = tid + 256 * i;
        const int row = u >> 2, seg = u & 3;
        cpa16(sst + G2_OFF_A + row * A_STRIDE + seg * 16, a + (size_t)row * lda + seg * 8);
    }
#pragma unroll
    for (int i = 0; i < 2; i++) {
        const int u = tid + 256 * i;
        const int row = u >> 4, seg = u & 15;
        cpa16(sst + G2_OFF_B + row * B_STRIDE + seg * 16, b + (size_t)row * ldb + seg * 8);
    }
    CP_COMMIT();
}

// gemm1 chunk: acc += A*Bh + A*Bl   (2-pass)
__device__ __forceinline__ void compute_chunk_g1(uint32_t sst, int lane, int wm, int wn,
                                                 float acc[4][4][4]) {
#pragma unroll
    for (int kk = 0; kk < 32; kk += 16) {
        uint32_t A[4][4], Bh[2][4], Bl[2][4];
        const uint32_t arow = wm * 64 + (lane & 7) + ((lane >> 3) & 1) * 8;
        const uint32_t acoff = (kk + (lane >> 4) * 8) * 2;
#pragma unroll
        for (int mi = 0; mi < 4; mi++)
            ldsm4(A[mi], sst + G1_OFF_A + (arow + mi * 16) * A_STRIDE + acoff);
        const uint32_t brow = kk + ((lane >> 3) & 1) * 8 + (lane & 7);
        const uint32_t bcoff = (wn * 32 + (lane >> 4) * 8) * 2;
#pragma unroll
        for (int np = 0; np < 2; np++) {
            const uint32_t bd = sst + G1_OFF_BH + brow * B_STRIDE + bcoff + np * 32;
            ldsm4t(Bh[np], bd);
            ldsm4t(Bl[np], bd + (G1_OFF_BL - G1_OFF_BH));
        }
#pragma unroll
        for (int mi = 0; mi < 4; mi++)
#pragma unroll
            for (int ni = 0; ni < 4; ni++)
                mma16816(acc[mi][ni], A[mi], Bh[ni >> 1][(ni & 1) * 2], Bh[ni >> 1][(ni & 1) * 2 + 1]);
#pragma unroll
        for (int mi = 0; mi < 4; mi++)
#pragma unroll
            for (int ni = 0; ni < 4; ni++)
                mma16816(acc[mi][ni], A[mi], Bl[ni >> 1][(ni & 1) * 2], Bl[ni >> 1][(ni & 1) * 2 + 1]);
    }
}

// gemm2 chunk: acc += A*B   (single pass)
__device__ __forceinline__ void compute_chunk_g2(uint32_t sst, int lane, int wm, int wn,
                                                 float acc[4][4][4]) {
#pragma unroll
    for (int kk = 0; kk < 32; kk += 16) {
        uint32_t A[4][4], B[2][4];
        const uint32_t arow = wm * 64 + (lane & 7) + ((lane >> 3) & 1) * 8;
        const uint32_t acoff = (kk + (lane >> 4) * 8) * 2;
#pragma unroll
        for (int mi = 0; mi < 4; mi++)
            ldsm4(A[mi], sst + G2_OFF_A + (arow + mi * 16) * A_STRIDE + acoff);
        const uint32_t brow = kk + ((lane >> 3) & 1) * 8 + (lane & 7);
        const uint32_t bcoff = (wn * 32 + (lane >> 4) * 8) * 2;
#pragma unroll
        for (int np = 0; np < 2; np++)
            ldsm4t(B[np], sst + G2_OFF_B + brow * B_STRIDE + bcoff + np * 32);
#pragma unroll
        for (int mi = 0; mi < 4; mi++)
#pragma unroll
            for (int ni = 0; ni < 4; ni++)
                mma16816(acc[mi][ni], A[mi], B[ni >> 1][(ni & 1) * 2], B[ni >> 1][(ni & 1) * 2 + 1]);
    }
}

// ---------------------------------------------------------------------------
// GEMM1: feats[h] = X @ W[h]; 2-pass. Epilogue: fp16 feats + fused s-dot
// partials (from exact fp32 acc) via atomicAdd.
// ---------------------------------------------------------------------------
__global__ __launch_bounds__(256, 2) void gemm1_mma(const float* __restrict__ a_self,
                                                    const float* __restrict__ a_neigh) {
    extern __shared__ char smem[];
    const int tid = threadIdx.x, lane = tid & 31, wid = tid >> 5;
    const int wm = wid >> 2, wn = wid & 3;
    const uint32_t sb = smem_u32(smem);
    const int cT = blockIdx.x, rT = blockIdx.y, h = blockIdx.z;

    const __half* A  = g_xhi + (size_t)rT * 128 * FF;
    const __half* Bh = g_whi + (size_t)h * FF * FK + (size_t)cT * 128;
    const __half* Bl = g_wlo + (size_t)h * FF * FK + (size_t)cT * 128;

    float acc[4][4][4];
#pragma unroll
    for (int i = 0; i < 4; i++)
#pragma unroll
        for (int j = 0; j < 4; j++)
#pragma unroll
            for (int k = 0; k < 4; k++) acc[i][j][k] = 0.f;

    const int NC = FF / 32;  // 16
    load_chunk_g1(sb, tid, A, Bh, Bl, FF, FK);
    load_chunk_g1(sb + G1_STAGE, tid, A + 32,
                  Bh + (size_t)32 * FK, Bl + (size_t)32 * FK, FF, FK);

    for (int c = 0; c < NC; c++) {
        if (c < NC - 1) asm volatile("cp.async.wait_group 1;" ::: "memory");
        else            asm volatile("cp.async.wait_group 0;" ::: "memory");
        __syncthreads();
        if (c + 2 < NC) {
            const int cn = c + 2;
            load_chunk_g1(sb + (cn % 3) * G1_STAGE, tid, A + cn * 32,
                          Bh + (size_t)(cn * 32) * FK, Bl + (size_t)(cn * 32) * FK, FF, FK);
        }
        compute_chunk_g1(sb + (c % 3) * G1_STAGE, lane, wm, wn, acc);
        __syncthreads();
    }

    const int b = rT >> 3;
    const int hb = h * BATCH + b;
    const size_t fbase = ((size_t)hb << 20);
    const int nrow0 = (rT & 7) * 128;

    // preload the 16 attention-vector entries this thread touches
    const float* asv = a_self + h * FK;
    const float* anv = a_neigh + h * FK;
    float av[4][2], nv[4][2];
#pragma unroll
    for (int ni = 0; ni < 4; ni++) {
        const int col = cT * 128 + wn * 32 + ni * 8 + (lane & 3) * 2;
#pragma unroll
        for (int j = 0; j < 2; j++) {
            av[ni][j] = asv[col + j];
            nv[ni][j] = anv[col + j];
        }
    }

#pragma unroll
    for (int mi = 0; mi < 4; mi++) {
#pragma unroll
        for (int half = 0; half < 2; half++) {
            // s-dot partial over this thread's 8 columns (exact fp32 feats)
            float s0 = 0.f, s1 = 0.f;
#pragma unroll
            for (int ni = 0; ni < 4; ni++) {
#pragma unroll
                for (int j = 0; j < 2; j++) {
                    const float v = acc[mi][ni][half * 2 + j];
                    s0 += v * av[ni][j];
                    s1 += v * nv[ni][j];
                }
            }
            s0 += __shfl_xor_sync(0xFFFFFFFFu, s0, 1);
            s0 += __shfl_xor_sync(0xFFFFFFFFu, s0, 2);
            s1 += __shfl_xor_sync(0xFFFFFFFFu, s1, 1);
            s1 += __shfl_xor_sync(0xFFFFFFFFu, s1, 2);
            if ((lane & 3) == 0) {
                const int n = nrow0 + wm * 64 + mi * 16 + (lane >> 2) + half * 8;
                atomicAdd(&g_sself[hb * NN + n], s0);
                atomicAdd(&g_sneigh[hb * NN + n], s1);
            }
        }
        // fp16 feats store
#pragma unroll
        for (int ni = 0; ni < 4; ni++) {
            const int row0 = wm * 64 + mi * 16 + (lane >> 2);
            const int col0 = cT * 128 + wn * 32 + ni * 8 + (lane & 3) * 2;
#pragma unroll
            for (int half = 0; half < 2; half++) {
                const int n = nrow0 + row0 + half * 8;
                const uint32_t ph = pack_h2(acc[mi][ni][half * 2], acc[mi][ni][half * 2 + 1]);
                *reinterpret_cast<uint32_t*>(g_fhi + fbase + (size_t)n * FK + col0) = ph;
            }
        }
    }
}

// ---------------------------------------------------------------------------
// GEMM2: out[b] = (1/3) sum_h attn[h,b] @ feats_hi[h,b] + mean bias ; 1-pass
// ---------------------------------------------------------------------------
__global__ __launch_bounds__(256, 2) void gemm2_mma(const float* __restrict__ biases,
                                                    float* __restrict__ out) {
    extern __shared__ char smem[];
    const int tid = threadIdx.x, lane = tid & 31, wid = tid >> 5;
    const int wm = wid >> 2, wn = wid & 3;
    const uint32_t sb = smem_u32(smem);
    const int cT = blockIdx.x, nT = blockIdx.y, b = blockIdx.z;

    float acc[4][4][4];
#pragma unroll
    for (int i = 0; i < 4; i++)
#pragma unroll
        for (int j = 0; j < 4; j++)
#pragma unroll
            for (int k = 0; k < 4; k++) acc[i][j][k] = 0.f;

    const int NC = 96;
    auto issue = [&](int cn) {
        const int hh = cn >> 5, kc = cn & 31;
        const size_t hb = ((size_t)(hh * BATCH + b)) << 20;
        load_chunk_g2(sb + (cn % 3) * G2_STAGE, tid,
                      g_ath + hb + ((size_t)nT << 17) + kc * 32,
                      g_fhi + hb + ((size_t)(kc * 32) << 10) + cT * 128, NN, FK);
    };
    issue(0);
    issue(1);

    for (int c = 0; c < NC; c++) {
        if (c < NC - 1) asm volatile("cp.async.wait_group 1;" ::: "memory");
        else            asm volatile("cp.async.wait_group 0;" ::: "memory");
        __syncthreads();
        if (c + 2 < NC) issue(c + 2);
        compute_chunk_g2(sb + (c % 3) * G2_STAGE, lane, wm, wn, acc);
        __syncthreads();
    }

    const float inv3 = 1.f / 3.f;
    const size_t obase = ((size_t)(H * BATCH + b) << 20) + ((size_t)nT << 17);
#pragma unroll
    for (int mi = 0; mi < 4; mi++)
#pragma unroll
        for (int ni = 0; ni < 4; ni++) {
            const int row0 = wm * 64 + mi * 16 + (lane >> 2);
            const int col0 = cT * 128 + wn * 32 + ni * 8 + (lane & 3) * 2;
            const float bm0 = (biases[col0] + biases[FK + col0] + biases[2 * FK + col0]) * inv3;
            const float bm1 = (biases[col0 + 1] + biases[FK + col0 + 1] + biases[2 * FK + col0 + 1]) * inv3;
#pragma unroll
            for (int half = 0; half < 2; half++) {
                const int n = row0 + half * 8;
                float2 v;
                v.x = acc[mi][ni][half * 2] * inv3 + bm0;
                v.y = acc[mi][ni][half * 2 + 1] * inv3 + bm1;
                *reinterpret_cast<float2*>(out + obase + (size_t)n * FK + col0) = v;
            }
        }
}

// ---------------------------------------------------------------------------
// prep: x -> fp16 (hi only); w -> fp16 hi/lo; zero s arrays
// ---------------------------------------------------------------------------
__global__ __launch_bounds__(1024) void split_x(const float* __restrict__ x) {
    const size_t i = (size_t)blockIdx.x * 1024 + threadIdx.x;
    g_xhi[i] = __float2half_rn(x[i]);
}
__global__ __launch_bounds__(1024) void split_w(const float* __restrict__ w) {
    const size_t i = (size_t)blockIdx.x * 1024 + threadIdx.x;
    const float v = w[i];
    const __half hv = __float2half_rn(v);
    g_whi[i] = hv;
    g_wlo[i] = __float2half_rn(v - __half2float(hv));
}
__global__ __launch_bounds__(1024) void zero_s() {
    const int i = blockIdx.x * 1024 + threadIdx.x;
    g_sself[i] = 0.f;
    g_sneigh[i] = 0.f;
}

// ---------------------------------------------------------------------------
// softmax: fp32 attn into out slab + single fp16 copy for GEMM2
// ---------------------------------------------------------------------------
__global__ __launch_bounds__(256) void softmax_kernel(float* __restrict__ out) {
    const int r = blockIdx.x;
    const int hb = r >> 10;
    const int tid = threadIdx.x;

    const float si = g_sself[r];
    const float* sn = g_sneigh + (size_t)hb * NN;

    __shared__ float redmax[8], redsum[8];
    __shared__ float bmax, bsum;

    float lv[4];
    float m = -1e30f;
#pragma unroll
    for (int jj = 0; jj < 4; jj++) {
        const int j = tid + jj * 256;
        float v = si + sn[j];
        v = (v >= 0.f) ? v : 0.2f * v;
        lv[jj] = v;
        m = fmaxf(m, v);
    }
#pragma unroll
    for (int o = 16; o; o >>= 1) m = fmaxf(m, __shfl_xor_sync(0xFFFFFFFFu, m, o));
    if ((tid & 31) == 0) redmax[tid >> 5] = m;
    __syncthreads();
    if (tid == 0) {
        float t = redmax[0];
#pragma unroll
        for (int i = 1; i < 8; i++) t = fmaxf(t, redmax[i]);
        bmax = t;
    }
    __syncthreads();
    m = bmax;

    float sum = 0.f;
#pragma unroll
    for (int jj = 0; jj < 4; jj++) {
        lv[jj] = __expf(lv[jj] - m);
        sum += lv[jj];
    }
#pragma unroll
    for (int o = 16; o; o >>= 1) sum += __shfl_xor_sync(0xFFFFFFFFu, sum, o);
    if ((tid & 31) == 0) redsum[tid >> 5] = sum;
    __syncthreads();
    if (tid == 0) {
        float t = 0.f;
#pragma unroll
        for (int i = 0; i < 8; i++) t += redsum[i];
        bsum = t;
    }
    __syncthreads();
    const float inv = 1.f / bsum;

    const size_t rowoff = ((size_t)hb << 20) + ((size_t)(r & 1023) << 10);
    float* orow = out + rowoff;
#pragma unroll
    for (int jj = 0; jj < 4; jj++) {
        const int j = tid + jj * 256;
        const float p = lv[jj] * inv;
        orow[j] = p;
        g_ath[rowoff + j] = __float2half_rn(p);
    }
}

// ---------------------------------------------------------------------------
extern "C" void kernel_launch(void* const* d_in, const int* in_sizes, int n_in,
                              void* d_out, int out_size) {
    const float* x       = (const float*)d_in[0];
    const float* kernels = (const float*)d_in[1];
    const float* biases  = (const float*)d_in[2];
    const float* a_self  = (const float*)d_in[3];
    const float* a_neigh = (const float*)d_in[4];
    float* out = (float*)d_out;

    static bool attr_set = false;
    if (!attr_set) {
        cudaFuncSetAttribute(gemm1_mma, cudaFuncAttributeMaxDynamicSharedMemorySize, SMEM1_BYTES);
        cudaFuncSetAttribute(gemm2_mma, cudaFuncAttributeMaxDynamicSharedMemorySize, SMEM2_BYTES);
        attr_set = true;
    }

    zero_s<<<(H * BATCH * NN) / 1024, 1024>>>();
    split_x<<<(M1 * FF) / 1024, 1024>>>(x);
    split_w<<<(H * FF * FK) / 1024, 1024>>>(kernels);

    gemm1_mma<<<dim3(FK / 128, M1 / 128, H), 256, SMEM1_BYTES>>>(a_self, a_neigh);

    softmax_kernel<<<H * BATCH * NN, 256>>>(out);

    gemm2_mma<<<dim3(FK / 128, NN / 128, BATCH), 256, SMEM2_BYTES>>>(biases, out);
}